// round 1
// baseline (speedup 1.0000x reference)
#include <cuda_runtime.h>
#include <math.h>

// Problem constants
#define BB   32
#define NTOK 1024
#define CCH  256
#define HH   4
#define DD   64
#define FF   1024
#define MROWS (BB * NTOK)   // 32768
#define EPSV 1e-5f

// ---------------- static device scratch (no allocations allowed) ----------------
__device__ float g_acc[1024];                 // [0:256) sum1, [256:512) sq1, [512:768) sum2, [768:1024) sq2
__device__ float g_scale1[CCH], g_shift1[CCH];
__device__ float g_scale2[CCH], g_shift2[CCH];
__device__ float g_Q  [(size_t)MROWS * CCH];  // (B,H,N,D)
__device__ float g_K  [(size_t)MROWS * CCH];
__device__ float g_V  [(size_t)MROWS * CCH];
__device__ float g_AO [(size_t)MROWS * CCH];  // attention out (B,N,C)
__device__ float g_R1 [(size_t)MROWS * CCH];  // residual 1
__device__ float g_MID[(size_t)MROWS * FF];   // MLP hidden

// ---------------- small kernels ----------------
__global__ void zero_acc_kernel() {
    g_acc[threadIdx.x] = 0.f;
}

// mean/var partial sums for BN1 over x
__global__ void bn_stats_kernel(const float* __restrict__ x) {
    int c  = threadIdx.x;           // 0..255
    int r0 = blockIdx.x * 128;      // 256 blocks
    const float* p = x + (size_t)r0 * CCH + c;
    float s = 0.f, q = 0.f;
#pragma unroll 4
    for (int i = 0; i < 128; i++) {
        float v = p[(size_t)i * CCH];
        s += v;
        q += v * v;
    }
    atomicAdd(&g_acc[c],        s);
    atomicAdd(&g_acc[CCH + c],  q);
}

// which==0 -> scale1/shift1 from acc[0..512), which==1 -> scale2/shift2 from acc[512..1024)
__global__ void bn_finalize_kernel(const float* __restrict__ g,
                                   const float* __restrict__ beta, int which) {
    int c = threadIdx.x;
    float invn = 1.f / (float)MROWS;
    float mean = g_acc[which * 512 + c] * invn;
    float var  = g_acc[which * 512 + 256 + c] * invn - mean * mean;
    float sc   = g[c] * rsqrtf(var + EPSV);
    float sh   = beta[c] - mean * sc;
    if (which == 0) { g_scale1[c] = sc; g_shift1[c] = sh; }
    else            { g_scale2[c] = sc; g_shift2[c] = sh; }
}

// ---------------- generic NT SGEMM: out[m,n] = sum_k A[m,k]*W[n,k] (+epilogue) ----------------
// EPI: 1 = +bias, store (B,H,N,D) QKV layout
//      2 = +bias +res, store row-major, accumulate BN2 stats into g_acc[512..1024)
//      3 = +bias, ReLU, store row-major
//      4 = +bias +res, store row-major (final output)
// TRA: apply per-k affine (scA,shA) to A on load (BatchNorm fused into GEMM)
template<int EPI, bool TRA>
__global__ __launch_bounds__(256)
void gemm_nt(const float* __restrict__ A, const float* __restrict__ Bw,
             const float* __restrict__ bias, const float* __restrict__ res,
             float* __restrict__ out, int M, int N, int K,
             const float* __restrict__ scA, const float* __restrict__ shA) {
    __shared__ float As[2][16][128];
    __shared__ float Bs[2][16][128];
    __shared__ float ssum[128];
    __shared__ float ssq[128];

    const int tid = threadIdx.x;
    const int tx = tid & 15;
    const int ty = tid >> 4;
    const int bx = blockIdx.x;   // N tile
    const int by = blockIdx.y;   // M tile

    const float* Ap = A  + (size_t)by * 128 * K;
    const float* Bp = Bw + (size_t)bx * 128 * K;

    if (EPI == 2 && tid < 128) { ssum[tid] = 0.f; ssq[tid] = 0.f; }

    // staging registers: each thread loads 2 float4 of A and 2 of B per tile
    const int lrow = tid >> 1;            // 0..127
    const int lc0  = (tid & 1) * 8;       // 0 or 8 (two consecutive float4)
    float4 sa0, sa1, sb0, sb1;

    float acc[8][8];
#pragma unroll
    for (int i = 0; i < 8; i++)
#pragma unroll
        for (int j = 0; j < 8; j++) acc[i][j] = 0.f;

#define FETCH_TILE(KT)                                                          \
    do {                                                                        \
        const float* ar = Ap + (size_t)lrow * K + (KT) + lc0;                   \
        const float* br = Bp + (size_t)lrow * K + (KT) + lc0;                   \
        sa0 = *(const float4*)(ar);     sa1 = *(const float4*)(ar + 4);         \
        sb0 = *(const float4*)(br);     sb1 = *(const float4*)(br + 4);         \
    } while (0)

#define STORE_TILE(BUF, KT)                                                     \
    do {                                                                        \
        float av[8] = {sa0.x, sa0.y, sa0.z, sa0.w, sa1.x, sa1.y, sa1.z, sa1.w}; \
        float bv[8] = {sb0.x, sb0.y, sb0.z, sb0.w, sb1.x, sb1.y, sb1.z, sb1.w}; \
        _Pragma("unroll")                                                       \
        for (int u = 0; u < 8; u++) {                                           \
            float t = av[u];                                                    \
            if (TRA) t = t * scA[(KT) + lc0 + u] + shA[(KT) + lc0 + u];         \
            As[BUF][lc0 + u][lrow] = t;                                         \
            Bs[BUF][lc0 + u][lrow] = bv[u];                                     \
        }                                                                       \
    } while (0)

    FETCH_TILE(0);
    STORE_TILE(0, 0);
    __syncthreads();

    int buf = 0;
    for (int kt = 0; kt < K; kt += 16) {
        const int nkt = kt + 16;
        const bool hasNext = nkt < K;
        if (hasNext) FETCH_TILE(nkt);

#pragma unroll
        for (int kk = 0; kk < 16; kk++) {
            float a[8], b[8];
            *(float4*)&a[0] = *(const float4*)&As[buf][kk][ty * 8];
            *(float4*)&a[4] = *(const float4*)&As[buf][kk][ty * 8 + 4];
            *(float4*)&b[0] = *(const float4*)&Bs[buf][kk][tx * 8];
            *(float4*)&b[4] = *(const float4*)&Bs[buf][kk][tx * 8 + 4];
#pragma unroll
            for (int i = 0; i < 8; i++)
#pragma unroll
                for (int j = 0; j < 8; j++)
                    acc[i][j] += a[i] * b[j];
        }

        if (hasNext) {
            STORE_TILE(buf ^ 1, nkt);
            __syncthreads();
            buf ^= 1;
        }
    }
#undef FETCH_TILE
#undef STORE_TILE

    // epilogue
    const int row0 = by * 128 + ty * 8;
    const int col0 = bx * 128 + tx * 8;
#pragma unroll
    for (int j = 0; j < 8; j++) {
        const int c = col0 + j;
        const float bvl = bias[c];
        float cs = 0.f, cq = 0.f;
#pragma unroll
        for (int i = 0; i < 8; i++) {
            const int m = row0 + i;
            float v = acc[i][j] + bvl;
            if (EPI == 2 || EPI == 4) v += res[(size_t)m * N + c];
            if (EPI == 3) v = fmaxf(v, 0.f);
            if (EPI == 1) {
                const int h = c >> 6, d = c & 63;
                const int b = m >> 10, n = m & 1023;
                out[(((size_t)(b * HH + h)) * NTOK + n) * DD + d] = v;
            } else {
                out[(size_t)m * N + c] = v;
            }
            if (EPI == 2) { cs += v; cq += v * v; }
        }
        if (EPI == 2) {
            atomicAdd(&ssum[tx * 8 + j], cs);
            atomicAdd(&ssq [tx * 8 + j], cq);
        }
    }
    if (EPI == 2) {
        __syncthreads();
        if (tid < 128) {
            atomicAdd(&g_acc[512 + bx * 128 + tid], ssum[tid]);
            atomicAdd(&g_acc[768 + bx * 128 + tid], ssq[tid]);
        }
    }
}

// ---------------- flash attention: one CTA per (b,h, 256 q rows) ----------------
__global__ __launch_bounds__(256, 1)
void attn_kernel(const float* __restrict__ Q, const float* __restrict__ Kg,
                 const float* __restrict__ Vg, float* __restrict__ O) {
    __shared__ float Ks[64][64];
    __shared__ float Vs[64][64];

    const int bh  = blockIdx.y;              // 0..127  (b*H + h)
    const int qt  = blockIdx.x;              // 0..3
    const int tid = threadIdx.x;             // row within q tile
    const size_t hoff = (size_t)bh * NTOK * DD;
    const float* Qh = Q  + hoff;
    const float* Kh = Kg + hoff;
    const float* Vh = Vg + hoff;
    const int qrow = qt * 256 + tid;

    float q[64];
#pragma unroll
    for (int d4 = 0; d4 < 16; d4++) {
        float4 t = *(const float4*)(Qh + (size_t)qrow * DD + d4 * 4);
        q[d4 * 4 + 0] = t.x * 0.125f;
        q[d4 * 4 + 1] = t.y * 0.125f;
        q[d4 * 4 + 2] = t.z * 0.125f;
        q[d4 * 4 + 3] = t.w * 0.125f;
    }

    float o[64];
#pragma unroll
    for (int d = 0; d < 64; d++) o[d] = 0.f;
    float mmax = -INFINITY, l = 0.f;

#pragma unroll 1
    for (int kt = 0; kt < NTOK; kt += 64) {
        __syncthreads();
#pragma unroll
        for (int i = 0; i < 4; i++) {
            const int lin = tid + i * 256;   // 0..1023
            const int r = lin >> 4, d4 = lin & 15;
            *(float4*)&Ks[r][d4 * 4] = *(const float4*)(Kh + (size_t)(kt + r) * DD + d4 * 4);
            *(float4*)&Vs[r][d4 * 4] = *(const float4*)(Vh + (size_t)(kt + r) * DD + d4 * 4);
        }
        __syncthreads();

#pragma unroll 1
        for (int j0 = 0; j0 < 64; j0 += 16) {
            float s[16];
#pragma unroll
            for (int j = 0; j < 16; j++) {
                const float4* kr = (const float4*)&Ks[j0 + j][0];
                float a = 0.f;
#pragma unroll
                for (int d4 = 0; d4 < 16; d4++) {
                    float4 kv = kr[d4];
                    a += q[d4 * 4 + 0] * kv.x;
                    a += q[d4 * 4 + 1] * kv.y;
                    a += q[d4 * 4 + 2] * kv.z;
                    a += q[d4 * 4 + 3] * kv.w;
                }
                s[j] = a;
            }
            float cm = s[0];
#pragma unroll
            for (int j = 1; j < 16; j++) cm = fmaxf(cm, s[j]);
            if (cm > mmax) {
                const float corr = __expf(mmax - cm);   // exp(-inf)=0 on first tile
                l *= corr;
#pragma unroll
                for (int d = 0; d < 64; d++) o[d] *= corr;
                mmax = cm;
            }
#pragma unroll
            for (int j = 0; j < 16; j++) {
                const float p = __expf(s[j] - mmax);
                l += p;
                const float4* vr = (const float4*)&Vs[j0 + j][0];
#pragma unroll
                for (int d4 = 0; d4 < 16; d4++) {
                    float4 vv = vr[d4];
                    o[d4 * 4 + 0] += p * vv.x;
                    o[d4 * 4 + 1] += p * vv.y;
                    o[d4 * 4 + 2] += p * vv.z;
                    o[d4 * 4 + 3] += p * vv.w;
                }
            }
        }
    }

    const float inv = 1.f / l;
    const int b = bh >> 2, h = bh & 3;
    float* op = O + ((size_t)(b * NTOK + qrow)) * CCH + h * DD;
#pragma unroll
    for (int d4 = 0; d4 < 16; d4++) {
        float4 t;
        t.x = o[d4 * 4 + 0] * inv;
        t.y = o[d4 * 4 + 1] * inv;
        t.z = o[d4 * 4 + 2] * inv;
        t.w = o[d4 * 4 + 3] * inv;
        *(float4*)(op + d4 * 4) = t;
    }
}

// ---------------- host launcher ----------------
extern "C" void kernel_launch(void* const* d_in, const int* in_sizes, int n_in,
                              void* d_out, int out_size) {
    const float* x     = (const float*)d_in[0];
    const float* wq    = (const float*)d_in[1];
    const float* bq    = (const float*)d_in[2];
    const float* wk    = (const float*)d_in[3];
    const float* bk    = (const float*)d_in[4];
    const float* wv    = (const float*)d_in[5];
    const float* bv    = (const float*)d_in[6];
    const float* wo    = (const float*)d_in[7];
    const float* bo    = (const float*)d_in[8];
    const float* g1    = (const float*)d_in[9];
    const float* beta1 = (const float*)d_in[10];
    const float* g2    = (const float*)d_in[11];
    const float* beta2 = (const float*)d_in[12];
    const float* w1    = (const float*)d_in[13];
    const float* bf1   = (const float*)d_in[14];
    const float* w2    = (const float*)d_in[15];
    const float* bf2   = (const float*)d_in[16];

    float *Qp, *Kp, *Vp, *AOp, *R1p, *MIDp, *SC1, *SH1, *SC2, *SH2;
    cudaGetSymbolAddress((void**)&Qp,   g_Q);
    cudaGetSymbolAddress((void**)&Kp,   g_K);
    cudaGetSymbolAddress((void**)&Vp,   g_V);
    cudaGetSymbolAddress((void**)&AOp,  g_AO);
    cudaGetSymbolAddress((void**)&R1p,  g_R1);
    cudaGetSymbolAddress((void**)&MIDp, g_MID);
    cudaGetSymbolAddress((void**)&SC1,  g_scale1);
    cudaGetSymbolAddress((void**)&SH1,  g_shift1);
    cudaGetSymbolAddress((void**)&SC2,  g_scale2);
    cudaGetSymbolAddress((void**)&SH2,  g_shift2);

    // BN1 stats
    zero_acc_kernel<<<1, 1024>>>();
    bn_stats_kernel<<<256, 256>>>(x);
    bn_finalize_kernel<<<1, 256>>>(g1, beta1, 0);

    // QKV projections (BN1 fused on A load), outputs in (B,H,N,D)
    gemm_nt<1, true><<<dim3(2, 256), 256>>>(x, wq, bq, nullptr, Qp, MROWS, CCH, CCH, SC1, SH1);
    gemm_nt<1, true><<<dim3(2, 256), 256>>>(x, wk, bk, nullptr, Kp, MROWS, CCH, CCH, SC1, SH1);
    gemm_nt<1, true><<<dim3(2, 256), 256>>>(x, wv, bv, nullptr, Vp, MROWS, CCH, CCH, SC1, SH1);

    // attention
    attn_kernel<<<dim3(4, BB * HH), 256>>>(Qp, Kp, Vp, AOp);

    // O projection + residual + BN2 stats
    gemm_nt<2, false><<<dim3(2, 256), 256>>>(AOp, wo, bo, x, R1p, MROWS, CCH, CCH, nullptr, nullptr);
    bn_finalize_kernel<<<1, 256>>>(g2, beta2, 1);

    // MLP
    gemm_nt<3, true ><<<dim3(8, 256), 256>>>(R1p, w1, bf1, nullptr, MIDp, MROWS, FF, CCH, SC2, SH2);
    gemm_nt<4, false><<<dim3(2, 256), 256>>>(MIDp, w2, bf2, R1p, (float*)d_out, MROWS, CCH, FF, nullptr, nullptr);
}

// round 3
// speedup vs baseline: 1.4623x; 1.4623x over previous
#include <cuda_runtime.h>
#include <math.h>
#include <stdint.h>

#define BB   32
#define NTOK 1024
#define CCH  256
#define HH   4
#define DD   64
#define FF   1024
#define MROWS (BB * NTOK)   // 32768
#define EPSV 1e-5f

// ---------------- static device scratch ----------------
__device__ float g_acc[1024];                 // [0:256) sum1, [256:512) sq1, [512:768) sum2, [768:1024) sq2
__device__ float g_scale1[CCH], g_shift1[CCH];
__device__ float g_scale2[CCH], g_shift2[CCH];
__device__ float g_Q  [(size_t)MROWS * CCH];  // (B,H,N,D)
__device__ float g_K  [(size_t)MROWS * CCH];
__device__ float g_V  [(size_t)MROWS * CCH];
__device__ float g_AO [(size_t)MROWS * CCH];  // attention out (B,N,C)
__device__ float g_R1 [(size_t)MROWS * CCH];  // residual 1
__device__ float g_MID[(size_t)MROWS * FF];   // MLP hidden

// ---------------- small kernels ----------------
__global__ void zero_acc_kernel() {
    g_acc[threadIdx.x] = 0.f;
}

__global__ void bn_stats_kernel(const float* __restrict__ x) {
    int c  = threadIdx.x;
    int r0 = blockIdx.x * 128;
    const float* p = x + (size_t)r0 * CCH + c;
    float s = 0.f, q = 0.f;
#pragma unroll 4
    for (int i = 0; i < 128; i++) {
        float v = p[(size_t)i * CCH];
        s += v;
        q += v * v;
    }
    atomicAdd(&g_acc[c],        s);
    atomicAdd(&g_acc[CCH + c],  q);
}

__global__ void bn_finalize_kernel(const float* __restrict__ g,
                                   const float* __restrict__ beta, int which) {
    int c = threadIdx.x;
    float invn = 1.f / (float)MROWS;
    float mean = g_acc[which * 512 + c] * invn;
    float var  = g_acc[which * 512 + 256 + c] * invn - mean * mean;
    float sc   = g[c] * rsqrtf(var + EPSV);
    float sh   = beta[c] - mean * sc;
    if (which == 0) { g_scale1[c] = sc; g_shift1[c] = sh; }
    else            { g_scale2[c] = sc; g_shift2[c] = sh; }
}

// ---------------- tf32 helpers ----------------
__device__ __forceinline__ uint32_t f2tf(float x) {
    uint32_t r;
    asm("cvt.rna.tf32.f32 %0, %1;" : "=r"(r) : "f"(x));
    return r;
}

__device__ __forceinline__ void mma8(float* c, const uint32_t* a, const uint32_t* b) {
    asm volatile(
        "mma.sync.aligned.m16n8k8.row.col.f32.tf32.tf32.f32 "
        "{%0,%1,%2,%3}, {%4,%5,%6,%7}, {%8,%9}, {%0,%1,%2,%3};"
        : "+f"(c[0]), "+f"(c[1]), "+f"(c[2]), "+f"(c[3])
        : "r"(a[0]), "r"(a[1]), "r"(a[2]), "r"(a[3]), "r"(b[0]), "r"(b[1]));
}

// ---------------- tf32 tensor-core NT GEMM: out[m,n] = sum_k A[m,k]*W[n,k] ----------------
// CTA tile 128x128, BK=32, 8 warps of 64x32. Smem XOR-swizzled (conflict-free frag LDS).
// EPI: 1 = +bias, store (B,H,N,D)   2 = +bias+res, store, BN2 stats
//      3 = +bias, ReLU              4 = +bias+res (final out)
// TRA: fused per-k affine on A (BatchNorm folded into GEMM load)
template<int EPI, bool TRA>
__global__ __launch_bounds__(256)
void gemm_tc(const float* __restrict__ A, const float* __restrict__ Bw,
             const float* __restrict__ bias, const float* __restrict__ res,
             float* __restrict__ out, int M, int N, int K,
             const float* __restrict__ scA, const float* __restrict__ shA) {
    extern __shared__ float smem[];            // As[2][4096] | Bs[2][4096]  (64 KB)
    __shared__ float ssum[128];
    __shared__ float ssq[128];

    const int tid  = threadIdx.x;
    const int lane = tid & 31;
    const int w    = tid >> 5;
    const int g    = lane >> 2;      // 0..7
    const int tk   = lane & 3;       // 0..3
    const int wm   = w & 1, wn = w >> 1;
    const int mw0  = wm * 64, nw0 = wn * 32;
    const int bx   = blockIdx.x, by = blockIdx.y;

    if (EPI == 2 && tid < 128) { ssum[tid] = 0.f; ssq[tid] = 0.f; }

    const int rowL = tid >> 1;               // 0..127
    const int colL = (tid & 1) * 16;         // 0 or 16
    const float* Apt = A  + (size_t)(by * 128 + rowL) * K + colL;
    const float* Bpt = Bw + (size_t)(bx * 128 + rowL) * K + colL;

    float4 ra[4], rb[4];
    float acc[4][4][4];
#pragma unroll
    for (int i = 0; i < 4; i++)
#pragma unroll
        for (int j = 0; j < 4; j++)
#pragma unroll
            for (int q = 0; q < 4; q++) acc[i][j][q] = 0.f;

#define FETCH(KT)                                                             \
    do {                                                                      \
        _Pragma("unroll")                                                     \
        for (int f = 0; f < 4; f++) {                                         \
            ra[f] = *(const float4*)(Apt + (KT) + f * 4);                     \
            rb[f] = *(const float4*)(Bpt + (KT) + f * 4);                     \
        }                                                                     \
    } while (0)

#define STORE(BUF, KT)                                                        \
    do {                                                                      \
        float* Asb = smem + (BUF) * 4096;                                     \
        float* Bsb = smem + 8192 + (BUF) * 4096;                              \
        const int dstbase = rowL * 32;                                        \
        const int sw = rowL & 7;                                              \
        _Pragma("unroll")                                                     \
        for (int f = 0; f < 4; f++) {                                         \
            int k4 = (colL >> 2) + f;                                         \
            float4 va = ra[f];                                                \
            if (TRA) {                                                        \
                int kk = (KT) + colL + f * 4;                                 \
                float4 s4 = *(const float4*)(scA + kk);                       \
                float4 h4 = *(const float4*)(shA + kk);                       \
                va.x = va.x * s4.x + h4.x;  va.y = va.y * s4.y + h4.y;        \
                va.z = va.z * s4.z + h4.z;  va.w = va.w * s4.w + h4.w;        \
            }                                                                 \
            uint4 ta; ta.x = f2tf(va.x); ta.y = f2tf(va.y);                   \
                      ta.z = f2tf(va.z); ta.w = f2tf(va.w);                   \
            float4 vb = rb[f];                                                \
            uint4 tb; tb.x = f2tf(vb.x); tb.y = f2tf(vb.y);                   \
                      tb.z = f2tf(vb.z); tb.w = f2tf(vb.w);                   \
            int dst = dstbase + ((k4 ^ sw) << 2);                             \
            *(uint4*)(Asb + dst) = ta;                                        \
            *(uint4*)(Bsb + dst) = tb;                                        \
        }                                                                     \
    } while (0)

    FETCH(0);
    STORE(0, 0);
    __syncthreads();

    int buf = 0;
    for (int kt = 0; kt < K; kt += 32) {
        const bool hn = (kt + 32) < K;
        if (hn) FETCH(kt + 32);

        const float* Asb = smem + buf * 4096;
        const float* Bsb = smem + 8192 + buf * 4096;
#pragma unroll
        for (int ks = 0; ks < 4; ks++) {
            const int o0 = (((ks * 2)     ^ g) << 2) + tk;
            const int o1 = (((ks * 2 + 1) ^ g) << 2) + tk;
            uint32_t bf[4][2];
#pragma unroll
            for (int j = 0; j < 4; j++) {
                const float* bp = Bsb + (nw0 + j * 8 + g) * 32;
                bf[j][0] = __float_as_uint(bp[o0]);
                bf[j][1] = __float_as_uint(bp[o1]);
            }
#pragma unroll
            for (int i = 0; i < 4; i++) {
                const float* ap = Asb + (mw0 + i * 16 + g) * 32;
                uint32_t af[4];
                af[0] = __float_as_uint(ap[o0]);
                af[1] = __float_as_uint(ap[o0 + 256]);
                af[2] = __float_as_uint(ap[o1]);
                af[3] = __float_as_uint(ap[o1 + 256]);
#pragma unroll
                for (int j = 0; j < 4; j++) mma8(acc[i][j], af, bf[j]);
            }
        }

        if (hn) {
            STORE(buf ^ 1, kt + 32);
            __syncthreads();
            buf ^= 1;
        }
    }
#undef FETCH
#undef STORE

    // ---------------- epilogue ----------------
    const int r_base = by * 128 + mw0 + g;
    const int c_glob = bx * 128 + nw0 + 2 * tk;
#pragma unroll
    for (int j = 0; j < 4; j++) {
        const int c0 = c_glob + j * 8;
        const float bv0 = bias[c0], bv1 = bias[c0 + 1];
        float cs0 = 0.f, cq0 = 0.f, cs1 = 0.f, cq1 = 0.f;
#pragma unroll
        for (int i = 0; i < 4; i++) {
#pragma unroll
            for (int rr = 0; rr < 2; rr++) {
                const int m = r_base + i * 16 + rr * 8;
                float v0 = acc[i][j][rr * 2 + 0] + bv0;
                float v1 = acc[i][j][rr * 2 + 1] + bv1;
                if (EPI == 2 || EPI == 4) {
                    const float2 rv = *(const float2*)(res + (size_t)m * N + c0);
                    v0 += rv.x; v1 += rv.y;
                }
                if (EPI == 3) { v0 = fmaxf(v0, 0.f); v1 = fmaxf(v1, 0.f); }
                if (EPI == 1) {
                    const int h = c0 >> 6, d = c0 & 63;
                    const int b = m >> 10, n = m & 1023;
                    float2 t; t.x = v0; t.y = v1;
                    *(float2*)(out + (((size_t)(b * HH + h) * NTOK + n) * DD + d)) = t;
                } else {
                    float2 t; t.x = v0; t.y = v1;
                    *(float2*)(out + (size_t)m * N + c0) = t;
                }
                if (EPI == 2) { cs0 += v0; cq0 += v0 * v0; cs1 += v1; cq1 += v1 * v1; }
            }
        }
        if (EPI == 2) {
            const int lc = nw0 + j * 8 + 2 * tk;
            atomicAdd(&ssum[lc],     cs0); atomicAdd(&ssq[lc],     cq0);
            atomicAdd(&ssum[lc + 1], cs1); atomicAdd(&ssq[lc + 1], cq1);
        }
    }
    if (EPI == 2) {
        __syncthreads();
        if (tid < 128) {
            atomicAdd(&g_acc[512 + bx * 128 + tid], ssum[tid]);
            atomicAdd(&g_acc[768 + bx * 128 + tid], ssq[tid]);
        }
    }
}

// ---------------- flash attention (SIMT, unchanged this round) ----------------
__global__ __launch_bounds__(256, 1)
void attn_kernel(const float* __restrict__ Q, const float* __restrict__ Kg,
                 const float* __restrict__ Vg, float* __restrict__ O) {
    __shared__ float Ks[64][64];
    __shared__ float Vs[64][64];

    const int bh  = blockIdx.y;
    const int qt  = blockIdx.x;
    const int tid = threadIdx.x;
    const size_t hoff = (size_t)bh * NTOK * DD;
    const float* Qh = Q  + hoff;
    const float* Kh = Kg + hoff;
    const float* Vh = Vg + hoff;
    const int qrow = qt * 256 + tid;

    float q[64];
#pragma unroll
    for (int d4 = 0; d4 < 16; d4++) {
        float4 t = *(const float4*)(Qh + (size_t)qrow * DD + d4 * 4);
        q[d4 * 4 + 0] = t.x * 0.125f;
        q[d4 * 4 + 1] = t.y * 0.125f;
        q[d4 * 4 + 2] = t.z * 0.125f;
        q[d4 * 4 + 3] = t.w * 0.125f;
    }

    float o[64];
#pragma unroll
    for (int d = 0; d < 64; d++) o[d] = 0.f;
    float mmax = -INFINITY, l = 0.f;

#pragma unroll 1
    for (int kt = 0; kt < NTOK; kt += 64) {
        __syncthreads();
#pragma unroll
        for (int i = 0; i < 4; i++) {
            const int lin = tid + i * 256;
            const int r = lin >> 4, d4 = lin & 15;
            *(float4*)&Ks[r][d4 * 4] = *(const float4*)(Kh + (size_t)(kt + r) * DD + d4 * 4);
            *(float4*)&Vs[r][d4 * 4] = *(const float4*)(Vh + (size_t)(kt + r) * DD + d4 * 4);
        }
        __syncthreads();

#pragma unroll 1
        for (int j0 = 0; j0 < 64; j0 += 16) {
            float s[16];
#pragma unroll
            for (int j = 0; j < 16; j++) {
                const float4* kr = (const float4*)&Ks[j0 + j][0];
                float a = 0.f;
#pragma unroll
                for (int d4 = 0; d4 < 16; d4++) {
                    float4 kv = kr[d4];
                    a += q[d4 * 4 + 0] * kv.x;
                    a += q[d4 * 4 + 1] * kv.y;
                    a += q[d4 * 4 + 2] * kv.z;
                    a += q[d4 * 4 + 3] * kv.w;
                }
                s[j] = a;
            }
            float cm = s[0];
#pragma unroll
            for (int j = 1; j < 16; j++) cm = fmaxf(cm, s[j]);
            if (cm > mmax) {
                const float corr = __expf(mmax - cm);
                l *= corr;
#pragma unroll
                for (int d = 0; d < 64; d++) o[d] *= corr;
                mmax = cm;
            }
#pragma unroll
            for (int j = 0; j < 16; j++) {
                const float p = __expf(s[j] - mmax);
                l += p;
                const float4* vr = (const float4*)&Vs[j0 + j][0];
#pragma unroll
                for (int d4 = 0; d4 < 16; d4++) {
                    float4 vv = vr[d4];
                    o[d4 * 4 + 0] += p * vv.x;
                    o[d4 * 4 + 1] += p * vv.y;
                    o[d4 * 4 + 2] += p * vv.z;
                    o[d4 * 4 + 3] += p * vv.w;
                }
            }
        }
    }

    const float inv = 1.f / l;
    const int b = bh >> 2, h = bh & 3;
    float* op = O + ((size_t)(b * NTOK + qrow)) * CCH + h * DD;
#pragma unroll
    for (int d4 = 0; d4 < 16; d4++) {
        float4 t;
        t.x = o[d4 * 4 + 0] * inv;
        t.y = o[d4 * 4 + 1] * inv;
        t.z = o[d4 * 4 + 2] * inv;
        t.w = o[d4 * 4 + 3] * inv;
        *(float4*)(op + d4 * 4) = t;
    }
}

// ---------------- host launcher ----------------
extern "C" void kernel_launch(void* const* d_in, const int* in_sizes, int n_in,
                              void* d_out, int out_size) {
    const float* x     = (const float*)d_in[0];
    const float* wq    = (const float*)d_in[1];
    const float* bq    = (const float*)d_in[2];
    const float* wk    = (const float*)d_in[3];
    const float* bk    = (const float*)d_in[4];
    const float* wv    = (const float*)d_in[5];
    const float* bv    = (const float*)d_in[6];
    const float* wo    = (const float*)d_in[7];
    const float* bo    = (const float*)d_in[8];
    const float* g1    = (const float*)d_in[9];
    const float* beta1 = (const float*)d_in[10];
    const float* g2    = (const float*)d_in[11];
    const float* beta2 = (const float*)d_in[12];
    const float* w1    = (const float*)d_in[13];
    const float* bf1   = (const float*)d_in[14];
    const float* w2    = (const float*)d_in[15];
    const float* bf2   = (const float*)d_in[16];

    float *Qp, *Kp, *Vp, *AOp, *R1p, *MIDp, *SC1, *SH1, *SC2, *SH2;
    cudaGetSymbolAddress((void**)&Qp,   g_Q);
    cudaGetSymbolAddress((void**)&Kp,   g_K);
    cudaGetSymbolAddress((void**)&Vp,   g_V);
    cudaGetSymbolAddress((void**)&AOp,  g_AO);
    cudaGetSymbolAddress((void**)&R1p,  g_R1);
    cudaGetSymbolAddress((void**)&MIDp, g_MID);
    cudaGetSymbolAddress((void**)&SC1,  g_scale1);
    cudaGetSymbolAddress((void**)&SH1,  g_shift1);
    cudaGetSymbolAddress((void**)&SC2,  g_scale2);
    cudaGetSymbolAddress((void**)&SH2,  g_shift2);

    const int SMEM = 65536;
    cudaFuncSetAttribute(gemm_tc<1, true >, cudaFuncAttributeMaxDynamicSharedMemorySize, SMEM);
    cudaFuncSetAttribute(gemm_tc<2, false>, cudaFuncAttributeMaxDynamicSharedMemorySize, SMEM);
    cudaFuncSetAttribute(gemm_tc<3, true >, cudaFuncAttributeMaxDynamicSharedMemorySize, SMEM);
    cudaFuncSetAttribute(gemm_tc<4, false>, cudaFuncAttributeMaxDynamicSharedMemorySize, SMEM);

    // BN1 stats
    zero_acc_kernel<<<1, 1024>>>();
    bn_stats_kernel<<<256, 256>>>(x);
    bn_finalize_kernel<<<1, 256>>>(g1, beta1, 0);

    // QKV projections (BN1 fused on A load), outputs in (B,H,N,D)
    gemm_tc<1, true ><<<dim3(2, 256), 256, SMEM>>>(x, wq, bq, nullptr, Qp, MROWS, CCH, CCH, SC1, SH1);
    gemm_tc<1, true ><<<dim3(2, 256), 256, SMEM>>>(x, wk, bk, nullptr, Kp, MROWS, CCH, CCH, SC1, SH1);
    gemm_tc<1, true ><<<dim3(2, 256), 256, SMEM>>>(x, wv, bv, nullptr, Vp, MROWS, CCH, CCH, SC1, SH1);

    // attention
    attn_kernel<<<dim3(4, BB * HH), 256>>>(Qp, Kp, Vp, AOp);

    // O projection + residual + BN2 stats
    gemm_tc<2, false><<<dim3(2, 256), 256, SMEM>>>(AOp, wo, bo, x, R1p, MROWS, CCH, CCH, nullptr, nullptr);
    bn_finalize_kernel<<<1, 256>>>(g2, beta2, 1);

    // MLP
    gemm_tc<3, true ><<<dim3(8, 256), 256, SMEM>>>(R1p, w1, bf1, nullptr, MIDp, MROWS, FF, CCH, SC2, SH2);
    gemm_tc<4, false><<<dim3(2, 256), 256, SMEM>>>(MIDp, w2, bf2, R1p, (float*)d_out, MROWS, CCH, FF, nullptr, nullptr);
}

// round 4
// speedup vs baseline: 2.6289x; 1.7977x over previous
#include <cuda_runtime.h>
#include <math.h>
#include <stdint.h>

#define BB   32
#define NTOK 1024
#define CCH  256
#define HH   4
#define DD   64
#define FF   1024
#define MROWS (BB * NTOK)   // 32768
#define EPSV 1e-5f

// ---------------- static device scratch ----------------
__device__ float g_acc[1024];                 // [0:256) sum1, [256:512) sq1, [512:768) sum2, [768:1024) sq2
__device__ float g_scale1[CCH], g_shift1[CCH];
__device__ float g_scale2[CCH], g_shift2[CCH];
__device__ float g_Q  [(size_t)MROWS * CCH];  // (B,H,N,D)
__device__ float g_K  [(size_t)MROWS * CCH];
__device__ float g_V  [(size_t)MROWS * CCH];
__device__ float g_AO [(size_t)MROWS * CCH];  // attention out (B,N,C)
__device__ float g_R1 [(size_t)MROWS * CCH];  // residual 1
__device__ float g_MID[(size_t)MROWS * FF];   // MLP hidden

// ---------------- small kernels ----------------
__global__ void zero_acc_kernel() {
    g_acc[threadIdx.x] = 0.f;
}

__global__ void bn_stats_kernel(const float* __restrict__ x) {
    int c  = threadIdx.x;
    int r0 = blockIdx.x * 128;
    const float* p = x + (size_t)r0 * CCH + c;
    float s = 0.f, q = 0.f;
#pragma unroll 4
    for (int i = 0; i < 128; i++) {
        float v = p[(size_t)i * CCH];
        s += v;
        q += v * v;
    }
    atomicAdd(&g_acc[c],        s);
    atomicAdd(&g_acc[CCH + c],  q);
}

__global__ void bn_finalize_kernel(const float* __restrict__ g,
                                   const float* __restrict__ beta, int which) {
    int c = threadIdx.x;
    float invn = 1.f / (float)MROWS;
    float mean = g_acc[which * 512 + c] * invn;
    float var  = g_acc[which * 512 + 256 + c] * invn - mean * mean;
    float sc   = g[c] * rsqrtf(var + EPSV);
    float sh   = beta[c] - mean * sc;
    if (which == 0) { g_scale1[c] = sc; g_shift1[c] = sh; }
    else            { g_scale2[c] = sc; g_shift2[c] = sh; }
}

// ---------------- tf32 helpers ----------------
__device__ __forceinline__ uint32_t f2tf(float x) {
    uint32_t r;
    asm("cvt.rna.tf32.f32 %0, %1;" : "=r"(r) : "f"(x));
    return r;
}

__device__ __forceinline__ void mma8(float* c, const uint32_t* a, const uint32_t* b) {
    asm volatile(
        "mma.sync.aligned.m16n8k8.row.col.f32.tf32.tf32.f32 "
        "{%0,%1,%2,%3}, {%4,%5,%6,%7}, {%8,%9}, {%0,%1,%2,%3};"
        : "+f"(c[0]), "+f"(c[1]), "+f"(c[2]), "+f"(c[3])
        : "r"(a[0]), "r"(a[1]), "r"(a[2]), "r"(a[3]), "r"(b[0]), "r"(b[1]));
}

// ---------------- tf32 tensor-core NT GEMM (unchanged from R3) ----------------
template<int EPI, bool TRA>
__global__ __launch_bounds__(256)
void gemm_tc(const float* __restrict__ A, const float* __restrict__ Bw,
             const float* __restrict__ bias, const float* __restrict__ res,
             float* __restrict__ out, int M, int N, int K,
             const float* __restrict__ scA, const float* __restrict__ shA) {
    extern __shared__ float smem[];            // As[2][4096] | Bs[2][4096]  (64 KB)
    __shared__ float ssum[128];
    __shared__ float ssq[128];

    const int tid  = threadIdx.x;
    const int lane = tid & 31;
    const int w    = tid >> 5;
    const int g    = lane >> 2;
    const int tk   = lane & 3;
    const int wm   = w & 1, wn = w >> 1;
    const int mw0  = wm * 64, nw0 = wn * 32;
    const int bx   = blockIdx.x, by = blockIdx.y;

    if (EPI == 2 && tid < 128) { ssum[tid] = 0.f; ssq[tid] = 0.f; }

    const int rowL = tid >> 1;
    const int colL = (tid & 1) * 16;
    const float* Apt = A  + (size_t)(by * 128 + rowL) * K + colL;
    const float* Bpt = Bw + (size_t)(bx * 128 + rowL) * K + colL;

    float4 ra[4], rb[4];
    float acc[4][4][4];
#pragma unroll
    for (int i = 0; i < 4; i++)
#pragma unroll
        for (int j = 0; j < 4; j++)
#pragma unroll
            for (int q = 0; q < 4; q++) acc[i][j][q] = 0.f;

#define FETCH(KT)                                                             \
    do {                                                                      \
        _Pragma("unroll")                                                     \
        for (int f = 0; f < 4; f++) {                                         \
            ra[f] = *(const float4*)(Apt + (KT) + f * 4);                     \
            rb[f] = *(const float4*)(Bpt + (KT) + f * 4);                     \
        }                                                                     \
    } while (0)

#define STORE(BUF, KT)                                                        \
    do {                                                                      \
        float* Asb = smem + (BUF) * 4096;                                     \
        float* Bsb = smem + 8192 + (BUF) * 4096;                              \
        const int dstbase = rowL * 32;                                        \
        const int sw = rowL & 7;                                              \
        _Pragma("unroll")                                                     \
        for (int f = 0; f < 4; f++) {                                         \
            int k4 = (colL >> 2) + f;                                         \
            float4 va = ra[f];                                                \
            if (TRA) {                                                        \
                int kk = (KT) + colL + f * 4;                                 \
                float4 s4 = *(const float4*)(scA + kk);                       \
                float4 h4 = *(const float4*)(shA + kk);                       \
                va.x = va.x * s4.x + h4.x;  va.y = va.y * s4.y + h4.y;        \
                va.z = va.z * s4.z + h4.z;  va.w = va.w * s4.w + h4.w;        \
            }                                                                 \
            uint4 ta; ta.x = f2tf(va.x); ta.y = f2tf(va.y);                   \
                      ta.z = f2tf(va.z); ta.w = f2tf(va.w);                   \
            float4 vb = rb[f];                                                \
            uint4 tb; tb.x = f2tf(vb.x); tb.y = f2tf(vb.y);                   \
                      tb.z = f2tf(vb.z); tb.w = f2tf(vb.w);                   \
            int dst = dstbase + ((k4 ^ sw) << 2);                             \
            *(uint4*)(Asb + dst) = ta;                                        \
            *(uint4*)(Bsb + dst) = tb;                                        \
        }                                                                     \
    } while (0)

    FETCH(0);
    STORE(0, 0);
    __syncthreads();

    int buf = 0;
    for (int kt = 0; kt < K; kt += 32) {
        const bool hn = (kt + 32) < K;
        if (hn) FETCH(kt + 32);

        const float* Asb = smem + buf * 4096;
        const float* Bsb = smem + 8192 + buf * 4096;
#pragma unroll
        for (int ks = 0; ks < 4; ks++) {
            const int o0 = (((ks * 2)     ^ g) << 2) + tk;
            const int o1 = (((ks * 2 + 1) ^ g) << 2) + tk;
            uint32_t bf[4][2];
#pragma unroll
            for (int j = 0; j < 4; j++) {
                const float* bp = Bsb + (nw0 + j * 8 + g) * 32;
                bf[j][0] = __float_as_uint(bp[o0]);
                bf[j][1] = __float_as_uint(bp[o1]);
            }
#pragma unroll
            for (int i = 0; i < 4; i++) {
                const float* ap = Asb + (mw0 + i * 16 + g) * 32;
                uint32_t af[4];
                af[0] = __float_as_uint(ap[o0]);
                af[1] = __float_as_uint(ap[o0 + 256]);
                af[2] = __float_as_uint(ap[o1]);
                af[3] = __float_as_uint(ap[o1 + 256]);
#pragma unroll
                for (int j = 0; j < 4; j++) mma8(acc[i][j], af, bf[j]);
            }
        }

        if (hn) {
            STORE(buf ^ 1, kt + 32);
            __syncthreads();
            buf ^= 1;
        }
    }
#undef FETCH
#undef STORE

    const int r_base = by * 128 + mw0 + g;
    const int c_glob = bx * 128 + nw0 + 2 * tk;
#pragma unroll
    for (int j = 0; j < 4; j++) {
        const int c0 = c_glob + j * 8;
        const float bv0 = bias[c0], bv1 = bias[c0 + 1];
        float cs0 = 0.f, cq0 = 0.f, cs1 = 0.f, cq1 = 0.f;
#pragma unroll
        for (int i = 0; i < 4; i++) {
#pragma unroll
            for (int rr = 0; rr < 2; rr++) {
                const int m = r_base + i * 16 + rr * 8;
                float v0 = acc[i][j][rr * 2 + 0] + bv0;
                float v1 = acc[i][j][rr * 2 + 1] + bv1;
                if (EPI == 2 || EPI == 4) {
                    const float2 rv = *(const float2*)(res + (size_t)m * N + c0);
                    v0 += rv.x; v1 += rv.y;
                }
                if (EPI == 3) { v0 = fmaxf(v0, 0.f); v1 = fmaxf(v1, 0.f); }
                if (EPI == 1) {
                    const int h = c0 >> 6, d = c0 & 63;
                    const int b = m >> 10, n = m & 1023;
                    float2 t; t.x = v0; t.y = v1;
                    *(float2*)(out + (((size_t)(b * HH + h) * NTOK + n) * DD + d)) = t;
                } else {
                    float2 t; t.x = v0; t.y = v1;
                    *(float2*)(out + (size_t)m * N + c0) = t;
                }
                if (EPI == 2) { cs0 += v0; cq0 += v0 * v0; cs1 += v1; cq1 += v1 * v1; }
            }
        }
        if (EPI == 2) {
            const int lc = nw0 + j * 8 + 2 * tk;
            atomicAdd(&ssum[lc],     cs0); atomicAdd(&ssq[lc],     cq0);
            atomicAdd(&ssum[lc + 1], cs1); atomicAdd(&ssq[lc + 1], cq1);
        }
    }
    if (EPI == 2) {
        __syncthreads();
        if (tid < 128) {
            atomicAdd(&g_acc[512 + bx * 128 + tid], ssum[tid]);
            atomicAdd(&g_acc[768 + bx * 128 + tid], ssq[tid]);
        }
    }
}

// ---------------- tensor-core flash attention ----------------
// One CTA per (b,h) and 128 q rows. 8 warps, each owns 16 q rows.
// Ks[128][68]: K tile (tf32 bits), pad-68 -> conflict-free frag loads.
// Vs[64][132]: V tile TRANSPOSED (dim-major, tf32 bits) -> direct B-operand for PV.
#define KS_STRIDE 68
#define VS_STRIDE 132
#define ATT_SMEM ((128 * KS_STRIDE + 64 * VS_STRIDE) * 4)

__global__ __launch_bounds__(256, 1)
void attn_tc(const float* __restrict__ Q, const float* __restrict__ Kg,
             const float* __restrict__ Vg, float* __restrict__ O) {
    extern __shared__ float smem[];
    float* Ks = smem;                       // 128*68
    float* Vs = smem + 128 * KS_STRIDE;     // 64*132

    const int tid  = threadIdx.x;
    const int lane = tid & 31;
    const int w    = tid >> 5;
    const int g    = lane >> 2;
    const int tk   = lane & 3;
    const int bh   = blockIdx.y;
    const int qt   = blockIdx.x;
    const int b    = bh >> 2, h = bh & 3;
    const size_t hoff = (size_t)bh * NTOK * DD;
    const float* Qh = Q  + hoff;
    const float* Kh = Kg + hoff;
    const float* Vh = Vg + hoff;
    const int q0 = qt * 128;

    float4 kst[8], vst[8];

#define AFETCH(KT)                                                              \
    do {                                                                        \
        _Pragma("unroll")                                                       \
        for (int i = 0; i < 8; i++) {                                           \
            const int lin = tid + 256 * i;                                      \
            const int kr = lin >> 4, c4 = lin & 15;                             \
            kst[i] = *(const float4*)(Kh + (size_t)((KT) + kr) * DD + c4 * 4);  \
            const int vc4 = lin >> 7, vk = lin & 127;                           \
            vst[i] = *(const float4*)(Vh + (size_t)((KT) + vk) * DD + vc4 * 4); \
        }                                                                       \
    } while (0)

#define ASTORE()                                                                \
    do {                                                                        \
        _Pragma("unroll")                                                       \
        for (int i = 0; i < 8; i++) {                                           \
            const int lin = tid + 256 * i;                                      \
            const int kr = lin >> 4, c4 = lin & 15;                             \
            uint4 t4; t4.x = f2tf(kst[i].x); t4.y = f2tf(kst[i].y);             \
                      t4.z = f2tf(kst[i].z); t4.w = f2tf(kst[i].w);             \
            *(uint4*)(Ks + kr * KS_STRIDE + c4 * 4) = t4;                       \
            const int vc4 = lin >> 7, vk = lin & 127;                           \
            Vs[(vc4 * 4 + 0) * VS_STRIDE + vk] = __uint_as_float(f2tf(vst[i].x)); \
            Vs[(vc4 * 4 + 1) * VS_STRIDE + vk] = __uint_as_float(f2tf(vst[i].y)); \
            Vs[(vc4 * 4 + 2) * VS_STRIDE + vk] = __uint_as_float(f2tf(vst[i].z)); \
            Vs[(vc4 * 4 + 3) * VS_STRIDE + vk] = __uint_as_float(f2tf(vst[i].w)); \
        }                                                                       \
    } while (0)

    // start first K/V fetch early; stage Q through Ks meanwhile
    AFETCH(0);

#pragma unroll
    for (int i = 0; i < 8; i++) {
        const int lin = tid + 256 * i;
        const int r = lin >> 4, c4 = lin & 15;
        float4 qv = *(const float4*)(Qh + (size_t)(q0 + r) * DD + c4 * 4);
        uint4 t4;
        t4.x = f2tf(qv.x * 0.125f); t4.y = f2tf(qv.y * 0.125f);
        t4.z = f2tf(qv.z * 0.125f); t4.w = f2tf(qv.w * 0.125f);
        *(uint4*)(Ks + r * KS_STRIDE + c4 * 4) = t4;
    }
    __syncthreads();

    uint32_t qa[8][4];
    {
        const float* qr0 = Ks + (w * 16 + g) * KS_STRIDE;
        const float* qr1 = qr0 + 8 * KS_STRIDE;
#pragma unroll
        for (int ks = 0; ks < 8; ks++) {
            qa[ks][0] = __float_as_uint(qr0[ks * 8 + tk]);
            qa[ks][1] = __float_as_uint(qr1[ks * 8 + tk]);
            qa[ks][2] = __float_as_uint(qr0[ks * 8 + tk + 4]);
            qa[ks][3] = __float_as_uint(qr1[ks * 8 + tk + 4]);
        }
    }

    float oacc[8][4];
#pragma unroll
    for (int n = 0; n < 8; n++)
#pragma unroll
        for (int q = 0; q < 4; q++) oacc[n][q] = 0.f;
    float m_g = -INFINITY, m_h = -INFINITY, l_g = 0.f, l_h = 0.f;

    const int src0 = (lane & 28) | (tk >> 1);
    const int src1 = src0 + 2;
    const bool odd = (tk & 1);

#pragma unroll 1
    for (int kt8 = 0; kt8 < 8; kt8++) {
        __syncthreads();          // previous tile fully consumed (and Q frags loaded)
        ASTORE();
        __syncthreads();
        if (kt8 < 7) AFETCH((kt8 + 1) * 128);

        // ---- S = Q K^T : 16 n-tiles x 8 k-steps ----
        float sacc[16][4];
#pragma unroll
        for (int j = 0; j < 16; j++)
#pragma unroll
            for (int q = 0; q < 4; q++) sacc[j][q] = 0.f;

#pragma unroll
        for (int j = 0; j < 16; j++) {
            const float* krow = Ks + (j * 8 + g) * KS_STRIDE;
#pragma unroll
            for (int ks = 0; ks < 8; ks++) {
                uint32_t kb[2];
                kb[0] = __float_as_uint(krow[ks * 8 + tk]);
                kb[1] = __float_as_uint(krow[ks * 8 + tk + 4]);
                mma8(sacc[j], qa[ks], kb);
            }
        }

        // ---- online softmax on fragments ----
        float tg = -INFINITY, th = -INFINITY;
#pragma unroll
        for (int j = 0; j < 16; j++) {
            tg = fmaxf(tg, fmaxf(sacc[j][0], sacc[j][1]));
            th = fmaxf(th, fmaxf(sacc[j][2], sacc[j][3]));
        }
        tg = fmaxf(tg, __shfl_xor_sync(0xffffffffu, tg, 1));
        tg = fmaxf(tg, __shfl_xor_sync(0xffffffffu, tg, 2));
        th = fmaxf(th, __shfl_xor_sync(0xffffffffu, th, 1));
        th = fmaxf(th, __shfl_xor_sync(0xffffffffu, th, 2));
        const float mg_new = fmaxf(m_g, tg);
        const float mh_new = fmaxf(m_h, th);
        const float cg = __expf(m_g - mg_new);
        const float ch = __expf(m_h - mh_new);
        m_g = mg_new; m_h = mh_new;
        l_g *= cg; l_h *= ch;
#pragma unroll
        for (int n = 0; n < 8; n++) {
            oacc[n][0] *= cg; oacc[n][1] *= cg;
            oacc[n][2] *= ch; oacc[n][3] *= ch;
        }
#pragma unroll
        for (int j = 0; j < 16; j++) {
            const float p0 = __expf(sacc[j][0] - m_g);
            const float p1 = __expf(sacc[j][1] - m_g);
            const float p2 = __expf(sacc[j][2] - m_h);
            const float p3 = __expf(sacc[j][3] - m_h);
            l_g += p0 + p1;  l_h += p2 + p3;
            sacc[j][0] = __uint_as_float(f2tf(p0));
            sacc[j][1] = __uint_as_float(f2tf(p1));
            sacc[j][2] = __uint_as_float(f2tf(p2));
            sacc[j][3] = __uint_as_float(f2tf(p3));
        }

        // ---- PV: quad-transpose P frags via shfl, then 8 dim-tiles ----
#pragma unroll
        for (int ks = 0; ks < 16; ks++) {
            const float e00 = __shfl_sync(0xffffffffu, sacc[ks][0], src0);
            const float e01 = __shfl_sync(0xffffffffu, sacc[ks][1], src0);
            const float e10 = __shfl_sync(0xffffffffu, sacc[ks][2], src0);
            const float e11 = __shfl_sync(0xffffffffu, sacc[ks][3], src0);
            const float f00 = __shfl_sync(0xffffffffu, sacc[ks][0], src1);
            const float f01 = __shfl_sync(0xffffffffu, sacc[ks][1], src1);
            const float f10 = __shfl_sync(0xffffffffu, sacc[ks][2], src1);
            const float f11 = __shfl_sync(0xffffffffu, sacc[ks][3], src1);
            uint32_t pa[4];
            pa[0] = __float_as_uint(odd ? e01 : e00);
            pa[1] = __float_as_uint(odd ? e11 : e10);
            pa[2] = __float_as_uint(odd ? f01 : f00);
            pa[3] = __float_as_uint(odd ? f11 : f10);
#pragma unroll
            for (int n = 0; n < 8; n++) {
                const float* vr = Vs + (n * 8 + g) * VS_STRIDE + ks * 8;
                uint32_t vb[2];
                vb[0] = __float_as_uint(vr[tk]);
                vb[1] = __float_as_uint(vr[tk + 4]);
                mma8(oacc[n], pa, vb);
            }
        }
    }
#undef AFETCH
#undef ASTORE

    // ---- finalize ----
    l_g += __shfl_xor_sync(0xffffffffu, l_g, 1);
    l_g += __shfl_xor_sync(0xffffffffu, l_g, 2);
    l_h += __shfl_xor_sync(0xffffffffu, l_h, 1);
    l_h += __shfl_xor_sync(0xffffffffu, l_h, 2);
    const float ig = 1.f / l_g;
    const float ih = 1.f / l_h;

    const int rg = b * NTOK + q0 + w * 16 + g;
    const int cbase = h * DD + 2 * tk;
#pragma unroll
    for (int n = 0; n < 8; n++) {
        float2 t0; t0.x = oacc[n][0] * ig; t0.y = oacc[n][1] * ig;
        *(float2*)(O + (size_t)rg * CCH + cbase + n * 8) = t0;
        float2 t1; t1.x = oacc[n][2] * ih; t1.y = oacc[n][3] * ih;
        *(float2*)(O + (size_t)(rg + 8) * CCH + cbase + n * 8) = t1;
    }
}

// ---------------- host launcher ----------------
extern "C" void kernel_launch(void* const* d_in, const int* in_sizes, int n_in,
                              void* d_out, int out_size) {
    const float* x     = (const float*)d_in[0];
    const float* wq    = (const float*)d_in[1];
    const float* bq    = (const float*)d_in[2];
    const float* wk    = (const float*)d_in[3];
    const float* bk    = (const float*)d_in[4];
    const float* wv    = (const float*)d_in[5];
    const float* bv    = (const float*)d_in[6];
    const float* wo    = (const float*)d_in[7];
    const float* bo    = (const float*)d_in[8];
    const float* g1    = (const float*)d_in[9];
    const float* beta1 = (const float*)d_in[10];
    const float* g2    = (const float*)d_in[11];
    const float* beta2 = (const float*)d_in[12];
    const float* w1    = (const float*)d_in[13];
    const float* bf1   = (const float*)d_in[14];
    const float* w2    = (const float*)d_in[15];
    const float* bf2   = (const float*)d_in[16];

    float *Qp, *Kp, *Vp, *AOp, *R1p, *MIDp, *SC1, *SH1, *SC2, *SH2;
    cudaGetSymbolAddress((void**)&Qp,   g_Q);
    cudaGetSymbolAddress((void**)&Kp,   g_K);
    cudaGetSymbolAddress((void**)&Vp,   g_V);
    cudaGetSymbolAddress((void**)&AOp,  g_AO);
    cudaGetSymbolAddress((void**)&R1p,  g_R1);
    cudaGetSymbolAddress((void**)&MIDp, g_MID);
    cudaGetSymbolAddress((void**)&SC1,  g_scale1);
    cudaGetSymbolAddress((void**)&SH1,  g_shift1);
    cudaGetSymbolAddress((void**)&SC2,  g_scale2);
    cudaGetSymbolAddress((void**)&SH2,  g_shift2);

    const int SMEM = 65536;
    cudaFuncSetAttribute(gemm_tc<1, true >, cudaFuncAttributeMaxDynamicSharedMemorySize, SMEM);
    cudaFuncSetAttribute(gemm_tc<2, false>, cudaFuncAttributeMaxDynamicSharedMemorySize, SMEM);
    cudaFuncSetAttribute(gemm_tc<3, true >, cudaFuncAttributeMaxDynamicSharedMemorySize, SMEM);
    cudaFuncSetAttribute(gemm_tc<4, false>, cudaFuncAttributeMaxDynamicSharedMemorySize, SMEM);
    cudaFuncSetAttribute(attn_tc,           cudaFuncAttributeMaxDynamicSharedMemorySize, ATT_SMEM);

    // BN1 stats
    zero_acc_kernel<<<1, 1024>>>();
    bn_stats_kernel<<<256, 256>>>(x);
    bn_finalize_kernel<<<1, 256>>>(g1, beta1, 0);

    // QKV projections (BN1 fused on A load), outputs in (B,H,N,D)
    gemm_tc<1, true ><<<dim3(2, 256), 256, SMEM>>>(x, wq, bq, nullptr, Qp, MROWS, CCH, CCH, SC1, SH1);
    gemm_tc<1, true ><<<dim3(2, 256), 256, SMEM>>>(x, wk, bk, nullptr, Kp, MROWS, CCH, CCH, SC1, SH1);
    gemm_tc<1, true ><<<dim3(2, 256), 256, SMEM>>>(x, wv, bv, nullptr, Vp, MROWS, CCH, CCH, SC1, SH1);

    // attention (tensor-core flash)
    attn_tc<<<dim3(NTOK / 128, BB * HH), 256, ATT_SMEM>>>(Qp, Kp, Vp, AOp);

    // O projection + residual + BN2 stats
    gemm_tc<2, false><<<dim3(2, 256), 256, SMEM>>>(AOp, wo, bo, x, R1p, MROWS, CCH, CCH, nullptr, nullptr);
    bn_finalize_kernel<<<1, 256>>>(g2, beta2, 1);

    // MLP
    gemm_tc<3, true ><<<dim3(8, 256), 256, SMEM>>>(R1p, w1, bf1, nullptr, MIDp, MROWS, FF, CCH, SC2, SH2);
    gemm_tc<4, false><<<dim3(2, 256), 256, SMEM>>>(MIDp, w2, bf2, R1p, (float*)d_out, MROWS, CCH, FF, nullptr, nullptr);
}

// round 6
// speedup vs baseline: 2.7568x; 1.0487x over previous
#include <cuda_runtime.h>
#include <math.h>
#include <stdint.h>

#define BB   32
#define NTOK 1024
#define CCH  256
#define HH   4
#define DD   64
#define FF   1024
#define MROWS (BB * NTOK)   // 32768
#define EPSV 1e-5f

// ---------------- static device scratch ----------------
__device__ float g_acc[1024];                 // [0:256) sum1, [256:512) sq1, [512:768) sum2, [768:1024) sq2
__device__ float g_scale1[CCH], g_shift1[CCH];
__device__ float g_scale2[CCH], g_shift2[CCH];
__device__ float g_Q  [(size_t)MROWS * CCH];  // (B,H,N,D)
__device__ float g_K  [(size_t)MROWS * CCH];
__device__ float g_V  [(size_t)MROWS * CCH];
__device__ float g_AO [(size_t)MROWS * CCH];  // attention out (B,N,C)
__device__ float g_R1 [(size_t)MROWS * CCH];  // residual 1
__device__ float g_MID[(size_t)MROWS * FF];   // MLP hidden

// ---------------- small kernels ----------------
__global__ void zero_acc_kernel() {
    g_acc[threadIdx.x] = 0.f;
}

__global__ void bn_stats_kernel(const float* __restrict__ x) {
    int c  = threadIdx.x;
    int r0 = blockIdx.x * 128;
    const float* p = x + (size_t)r0 * CCH + c;
    float s = 0.f, q = 0.f;
#pragma unroll 4
    for (int i = 0; i < 128; i++) {
        float v = p[(size_t)i * CCH];
        s += v;
        q += v * v;
    }
    atomicAdd(&g_acc[c],        s);
    atomicAdd(&g_acc[CCH + c],  q);
}

__global__ void bn_finalize_kernel(const float* __restrict__ g,
                                   const float* __restrict__ beta, int which) {
    int c = threadIdx.x;
    float invn = 1.f / (float)MROWS;
    float mean = g_acc[which * 512 + c] * invn;
    float var  = g_acc[which * 512 + 256 + c] * invn - mean * mean;
    float sc   = g[c] * rsqrtf(var + EPSV);
    float sh   = beta[c] - mean * sc;
    if (which == 0) { g_scale1[c] = sc; g_shift1[c] = sh; }
    else            { g_scale2[c] = sc; g_shift2[c] = sh; }
}

// ---------------- tf32 helpers ----------------
__device__ __forceinline__ uint32_t f2tf(float x) {
    uint32_t r;
    asm("cvt.rna.tf32.f32 %0, %1;" : "=r"(r) : "f"(x));
    return r;
}

__device__ __forceinline__ void mma8(float* c, const uint32_t* a, const uint32_t* b) {
    asm volatile(
        "mma.sync.aligned.m16n8k8.row.col.f32.tf32.tf32.f32 "
        "{%0,%1,%2,%3}, {%4,%5,%6,%7}, {%8,%9}, {%0,%1,%2,%3};"
        : "+f"(c[0]), "+f"(c[1]), "+f"(c[2]), "+f"(c[3])
        : "r"(a[0]), "r"(a[1]), "r"(a[2]), "r"(a[3]), "r"(b[0]), "r"(b[1]));
}

// ---------------- tf32 tensor-core NT GEMM ----------------
// CTA tile 128x128, BK=32, 8 warps of 64x32, 2 CTAs/SM (reg budget 128).
// Staging split: A-tile and B-tile fetched/stored in separate half-phases so
// only 4 float4 staging registers are live at a time.
template<int EPI, bool TRA>
__global__ __launch_bounds__(256, 2)
void gemm_tc(const float* __restrict__ A, const float* __restrict__ Bw,
             const float* __restrict__ bias, const float* __restrict__ res,
             float* __restrict__ out, int M, int N, int K,
             const float* __restrict__ scA, const float* __restrict__ shA) {
    extern __shared__ float smem[];            // As[2][4096] | Bs[2][4096]  (64 KB)
    __shared__ float ssum[128];
    __shared__ float ssq[128];

    const int tid  = threadIdx.x;
    const int lane = tid & 31;
    const int w    = tid >> 5;
    const int g    = lane >> 2;
    const int tk   = lane & 3;
    const int wm   = w & 1, wn = w >> 1;
    const int mw0  = wm * 64, nw0 = wn * 32;
    const int bx   = blockIdx.x, by = blockIdx.y;

    if (EPI == 2 && tid < 128) { ssum[tid] = 0.f; ssq[tid] = 0.f; }

    const int rowL = tid >> 1;
    const int colL = (tid & 1) * 16;
    const float* Apt = A  + (size_t)(by * 128 + rowL) * K + colL;
    const float* Bpt = Bw + (size_t)(bx * 128 + rowL) * K + colL;

    float4 ra[4], rb[4];
    float acc[4][4][4];
#pragma unroll
    for (int i = 0; i < 4; i++)
#pragma unroll
        for (int j = 0; j < 4; j++)
#pragma unroll
            for (int q = 0; q < 4; q++) acc[i][j][q] = 0.f;

#define FETCH_A(KT)                                                           \
    do {                                                                      \
        _Pragma("unroll")                                                     \
        for (int f = 0; f < 4; f++)                                           \
            ra[f] = *(const float4*)(Apt + (KT) + f * 4);                     \
    } while (0)

#define FETCH_B(KT)                                                           \
    do {                                                                      \
        _Pragma("unroll")                                                     \
        for (int f = 0; f < 4; f++)                                           \
            rb[f] = *(const float4*)(Bpt + (KT) + f * 4);                     \
    } while (0)

#define STORE_A(BUF, KT)                                                      \
    do {                                                                      \
        float* Asb = smem + (BUF) * 4096;                                     \
        const int dstbase = rowL * 32;                                        \
        const int sw = rowL & 7;                                              \
        _Pragma("unroll")                                                     \
        for (int f = 0; f < 4; f++) {                                         \
            int k4 = (colL >> 2) + f;                                         \
            float4 va = ra[f];                                                \
            if (TRA) {                                                        \
                int kk = (KT) + colL + f * 4;                                 \
                float4 s4 = *(const float4*)(scA + kk);                       \
                float4 h4 = *(const float4*)(shA + kk);                       \
                va.x = va.x * s4.x + h4.x;  va.y = va.y * s4.y + h4.y;        \
                va.z = va.z * s4.z + h4.z;  va.w = va.w * s4.w + h4.w;        \
            }                                                                 \
            uint4 ta; ta.x = f2tf(va.x); ta.y = f2tf(va.y);                   \
                      ta.z = f2tf(va.z); ta.w = f2tf(va.w);                   \
            *(uint4*)(Asb + dstbase + ((k4 ^ sw) << 2)) = ta;                 \
        }                                                                     \
    } while (0)

#define STORE_B(BUF)                                                          \
    do {                                                                      \
        float* Bsb = smem + 8192 + (BUF) * 4096;                              \
        const int dstbase = rowL * 32;                                        \
        const int sw = rowL & 7;                                              \
        _Pragma("unroll")                                                     \
        for (int f = 0; f < 4; f++) {                                         \
            int k4 = (colL >> 2) + f;                                         \
            float4 vb = rb[f];                                                \
            uint4 tb; tb.x = f2tf(vb.x); tb.y = f2tf(vb.y);                   \
                      tb.z = f2tf(vb.z); tb.w = f2tf(vb.w);                   \
            *(uint4*)(Bsb + dstbase + ((k4 ^ sw) << 2)) = tb;                 \
        }                                                                     \
    } while (0)

// one ks step of 16 mmas
#define COMPUTE_KS(KS)                                                        \
    do {                                                                      \
        const int o0 = ((((KS) * 2)     ^ g) << 2) + tk;                      \
        const int o1 = ((((KS) * 2 + 1) ^ g) << 2) + tk;                      \
        uint32_t bf[4][2];                                                    \
        _Pragma("unroll")                                                     \
        for (int j = 0; j < 4; j++) {                                         \
            const float* bp = Bsb + (nw0 + j * 8 + g) * 32;                   \
            bf[j][0] = __float_as_uint(bp[o0]);                               \
            bf[j][1] = __float_as_uint(bp[o1]);                               \
        }                                                                     \
        _Pragma("unroll")                                                     \
        for (int i = 0; i < 4; i++) {                                         \
            const float* ap = Asb + (mw0 + i * 16 + g) * 32;                  \
            uint32_t af[4];                                                   \
            af[0] = __float_as_uint(ap[o0]);                                  \
            af[1] = __float_as_uint(ap[o0 + 256]);                            \
            af[2] = __float_as_uint(ap[o1]);                                  \
            af[3] = __float_as_uint(ap[o1 + 256]);                            \
            _Pragma("unroll")                                                 \
            for (int j = 0; j < 4; j++) mma8(acc[i][j], af, bf[j]);           \
        }                                                                     \
    } while (0)

    FETCH_A(0);  STORE_A(0, 0);
    FETCH_B(0);  STORE_B(0);
    __syncthreads();

    int buf = 0;
    for (int kt = 0; kt < K; kt += 32) {
        const bool hn = (kt + 32) < K;
        const float* Asb = smem + buf * 4096;
        const float* Bsb = smem + 8192 + buf * 4096;

        if (hn) FETCH_A(kt + 32);
        COMPUTE_KS(0);
        COMPUTE_KS(1);
        if (hn) { STORE_A(buf ^ 1, kt + 32); FETCH_B(kt + 32); }
        COMPUTE_KS(2);
        COMPUTE_KS(3);
        if (hn) {
            STORE_B(buf ^ 1);
            __syncthreads();
            buf ^= 1;
        }
    }
#undef FETCH_A
#undef FETCH_B
#undef STORE_A
#undef STORE_B
#undef COMPUTE_KS

    // ---------------- epilogue ----------------
    const int r_base = by * 128 + mw0 + g;
    const int c_glob = bx * 128 + nw0 + 2 * tk;
#pragma unroll
    for (int j = 0; j < 4; j++) {
        const int c0 = c_glob + j * 8;
        const float bv0 = bias[c0], bv1 = bias[c0 + 1];
        float cs0 = 0.f, cq0 = 0.f, cs1 = 0.f, cq1 = 0.f;
#pragma unroll
        for (int i = 0; i < 4; i++) {
#pragma unroll
            for (int rr = 0; rr < 2; rr++) {
                const int m = r_base + i * 16 + rr * 8;
                float v0 = acc[i][j][rr * 2 + 0] + bv0;
                float v1 = acc[i][j][rr * 2 + 1] + bv1;
                if (EPI == 2 || EPI == 4) {
                    const float2 rv = *(const float2*)(res + (size_t)m * N + c0);
                    v0 += rv.x; v1 += rv.y;
                }
                if (EPI == 3) { v0 = fmaxf(v0, 0.f); v1 = fmaxf(v1, 0.f); }
                if (EPI == 1) {
                    const int h = c0 >> 6, d = c0 & 63;
                    const int b = m >> 10, n = m & 1023;
                    float2 t; t.x = v0; t.y = v1;
                    *(float2*)(out + (((size_t)(b * HH + h) * NTOK + n) * DD + d)) = t;
                } else {
                    float2 t; t.x = v0; t.y = v1;
                    *(float2*)(out + (size_t)m * N + c0) = t;
                }
                if (EPI == 2) { cs0 += v0; cq0 += v0 * v0; cs1 += v1; cq1 += v1 * v1; }
            }
        }
        if (EPI == 2) {
            const int lc = nw0 + j * 8 + 2 * tk;
            atomicAdd(&ssum[lc],     cs0); atomicAdd(&ssq[lc],     cq0);
            atomicAdd(&ssum[lc + 1], cs1); atomicAdd(&ssq[lc + 1], cq1);
        }
    }
    if (EPI == 2) {
        __syncthreads();
        if (tid < 128) {
            atomicAdd(&g_acc[512 + bx * 128 + tid], ssum[tid]);
            atomicAdd(&g_acc[768 + bx * 128 + tid], ssq[tid]);
        }
    }
}

// ---------------- tensor-core flash attention (unchanged from R4) ----------------
#define KS_STRIDE 68
#define VS_STRIDE 132
#define ATT_SMEM ((128 * KS_STRIDE + 64 * VS_STRIDE) * 4)

__global__ __launch_bounds__(256, 1)
void attn_tc(const float* __restrict__ Q, const float* __restrict__ Kg,
             const float* __restrict__ Vg, float* __restrict__ O) {
    extern __shared__ float smem[];
    float* Ks = smem;                       // 128*68
    float* Vs = smem + 128 * KS_STRIDE;     // 64*132

    const int tid  = threadIdx.x;
    const int lane = tid & 31;
    const int w    = tid >> 5;
    const int g    = lane >> 2;
    const int tk   = lane & 3;
    const int bh   = blockIdx.y;
    const int qt   = blockIdx.x;
    const int b    = bh >> 2, h = bh & 3;
    const size_t hoff = (size_t)bh * NTOK * DD;
    const float* Qh = Q  + hoff;
    const float* Kh = Kg + hoff;
    const float* Vh = Vg + hoff;
    const int q0 = qt * 128;

    float4 kst[8], vst[8];

#define AFETCH(KT)                                                              \
    do {                                                                        \
        _Pragma("unroll")                                                       \
        for (int i = 0; i < 8; i++) {                                           \
            const int lin = tid + 256 * i;                                      \
            const int kr = lin >> 4, c4 = lin & 15;                             \
            kst[i] = *(const float4*)(Kh + (size_t)((KT) + kr) * DD + c4 * 4);  \
            const int vc4 = lin >> 7, vk = lin & 127;                           \
            vst[i] = *(const float4*)(Vh + (size_t)((KT) + vk) * DD + vc4 * 4); \
        }                                                                       \
    } while (0)

#define ASTORE()                                                                \
    do {                                                                        \
        _Pragma("unroll")                                                       \
        for (int i = 0; i < 8; i++) {                                           \
            const int lin = tid + 256 * i;                                      \
            const int kr = lin >> 4, c4 = lin & 15;                             \
            uint4 t4; t4.x = f2tf(kst[i].x); t4.y = f2tf(kst[i].y);             \
                      t4.z = f2tf(kst[i].z); t4.w = f2tf(kst[i].w);             \
            *(uint4*)(Ks + kr * KS_STRIDE + c4 * 4) = t4;                       \
            const int vc4 = lin >> 7, vk = lin & 127;                           \
            Vs[(vc4 * 4 + 0) * VS_STRIDE + vk] = __uint_as_float(f2tf(vst[i].x)); \
            Vs[(vc4 * 4 + 1) * VS_STRIDE + vk] = __uint_as_float(f2tf(vst[i].y)); \
            Vs[(vc4 * 4 + 2) * VS_STRIDE + vk] = __uint_as_float(f2tf(vst[i].z)); \
            Vs[(vc4 * 4 + 3) * VS_STRIDE + vk] = __uint_as_float(f2tf(vst[i].w)); \
        }                                                                       \
    } while (0)

    AFETCH(0);

#pragma unroll
    for (int i = 0; i < 8; i++) {
        const int lin = tid + 256 * i;
        const int r = lin >> 4, c4 = lin & 15;
        float4 qv = *(const float4*)(Qh + (size_t)(q0 + r) * DD + c4 * 4);
        uint4 t4;
        t4.x = f2tf(qv.x * 0.125f); t4.y = f2tf(qv.y * 0.125f);
        t4.z = f2tf(qv.z * 0.125f); t4.w = f2tf(qv.w * 0.125f);
        *(uint4*)(Ks + r * KS_STRIDE + c4 * 4) = t4;
    }
    __syncthreads();

    uint32_t qa[8][4];
    {
        const float* qr0 = Ks + (w * 16 + g) * KS_STRIDE;
        const float* qr1 = qr0 + 8 * KS_STRIDE;
#pragma unroll
        for (int ks = 0; ks < 8; ks++) {
            qa[ks][0] = __float_as_uint(qr0[ks * 8 + tk]);
            qa[ks][1] = __float_as_uint(qr1[ks * 8 + tk]);
            qa[ks][2] = __float_as_uint(qr0[ks * 8 + tk + 4]);
            qa[ks][3] = __float_as_uint(qr1[ks * 8 + tk + 4]);
        }
    }

    float oacc[8][4];
#pragma unroll
    for (int n = 0; n < 8; n++)
#pragma unroll
        for (int q = 0; q < 4; q++) oacc[n][q] = 0.f;
    float m_g = -INFINITY, m_h = -INFINITY, l_g = 0.f, l_h = 0.f;

    const int src0 = (lane & 28) | (tk >> 1);
    const int src1 = src0 + 2;
    const bool odd = (tk & 1);

#pragma unroll 1
    for (int kt8 = 0; kt8 < 8; kt8++) {
        __syncthreads();
        ASTORE();
        __syncthreads();
        if (kt8 < 7) AFETCH((kt8 + 1) * 128);

        float sacc[16][4];
#pragma unroll
        for (int j = 0; j < 16; j++)
#pragma unroll
            for (int q = 0; q < 4; q++) sacc[j][q] = 0.f;

#pragma unroll
        for (int j = 0; j < 16; j++) {
            const float* krow = Ks + (j * 8 + g) * KS_STRIDE;
#pragma unroll
            for (int ks = 0; ks < 8; ks++) {
                uint32_t kb[2];
                kb[0] = __float_as_uint(krow[ks * 8 + tk]);
                kb[1] = __float_as_uint(krow[ks * 8 + tk + 4]);
                mma8(sacc[j], qa[ks], kb);
            }
        }

        float tg = -INFINITY, th = -INFINITY;
#pragma unroll
        for (int j = 0; j < 16; j++) {
            tg = fmaxf(tg, fmaxf(sacc[j][0], sacc[j][1]));
            th = fmaxf(th, fmaxf(sacc[j][2], sacc[j][3]));
        }
        tg = fmaxf(tg, __shfl_xor_sync(0xffffffffu, tg, 1));
        tg = fmaxf(tg, __shfl_xor_sync(0xffffffffu, tg, 2));
        th = fmaxf(th, __shfl_xor_sync(0xffffffffu, th, 1));
        th = fmaxf(th, __shfl_xor_sync(0xffffffffu, th, 2));
        const float mg_new = fmaxf(m_g, tg);
        const float mh_new = fmaxf(m_h, th);
        const float cg = __expf(m_g - mg_new);
        const float ch = __expf(m_h - mh_new);
        m_g = mg_new; m_h = mh_new;
        l_g *= cg; l_h *= ch;
#pragma unroll
        for (int n = 0; n < 8; n++) {
            oacc[n][0] *= cg; oacc[n][1] *= cg;
            oacc[n][2] *= ch; oacc[n][3] *= ch;
        }
#pragma unroll
        for (int j = 0; j < 16; j++) {
            const float p0 = __expf(sacc[j][0] - m_g);
            const float p1 = __expf(sacc[j][1] - m_g);
            const float p2 = __expf(sacc[j][2] - m_h);
            const float p3 = __expf(sacc[j][3] - m_h);
            l_g += p0 + p1;  l_h += p2 + p3;
            sacc[j][0] = __uint_as_float(f2tf(p0));
            sacc[j][1] = __uint_as_float(f2tf(p1));
            sacc[j][2] = __uint_as_float(f2tf(p2));
            sacc[j][3] = __uint_as_float(f2tf(p3));
        }

#pragma unroll
        for (int ks = 0; ks < 16; ks++) {
            const float e00 = __shfl_sync(0xffffffffu, sacc[ks][0], src0);
            const float e01 = __shfl_sync(0xffffffffu, sacc[ks][1], src0);
            const float e10 = __shfl_sync(0xffffffffu, sacc[ks][2], src0);
            const float e11 = __shfl_sync(0xffffffffu, sacc[ks][3], src0);
            const float f00 = __shfl_sync(0xffffffffu, sacc[ks][0], src1);
            const float f01 = __shfl_sync(0xffffffffu, sacc[ks][1], src1);
            const float f10 = __shfl_sync(0xffffffffu, sacc[ks][2], src1);
            const float f11 = __shfl_sync(0xffffffffu, sacc[ks][3], src1);
            uint32_t pa[4];
            pa[0] = __float_as_uint(odd ? e01 : e00);
            pa[1] = __float_as_uint(odd ? e11 : e10);
            pa[2] = __float_as_uint(odd ? f01 : f00);
            pa[3] = __float_as_uint(odd ? f11 : f10);
#pragma unroll
            for (int n = 0; n < 8; n++) {
                const float* vr = Vs + (n * 8 + g) * VS_STRIDE + ks * 8;
                uint32_t vb[2];
                vb[0] = __float_as_uint(vr[tk]);
                vb[1] = __float_as_uint(vr[tk + 4]);
                mma8(oacc[n], pa, vb);
            }
        }
    }
#undef AFETCH
#undef ASTORE

    l_g += __shfl_xor_sync(0xffffffffu, l_g, 1);
    l_g += __shfl_xor_sync(0xffffffffu, l_g, 2);
    l_h += __shfl_xor_sync(0xffffffffu, l_h, 1);
    l_h += __shfl_xor_sync(0xffffffffu, l_h, 2);
    const float ig = 1.f / l_g;
    const float ih = 1.f / l_h;

    const int rg = b * NTOK + q0 + w * 16 + g;
    const int cbase = h * DD + 2 * tk;
#pragma unroll
    for (int n = 0; n < 8; n++) {
        float2 t0; t0.x = oacc[n][0] * ig; t0.y = oacc[n][1] * ig;
        *(float2*)(O + (size_t)rg * CCH + cbase + n * 8) = t0;
        float2 t1; t1.x = oacc[n][2] * ih; t1.y = oacc[n][3] * ih;
        *(float2*)(O + (size_t)(rg + 8) * CCH + cbase + n * 8) = t1;
    }
}

// ---------------- host launcher ----------------
extern "C" void kernel_launch(void* const* d_in, const int* in_sizes, int n_in,
                              void* d_out, int out_size) {
    const float* x     = (const float*)d_in[0];
    const float* wq    = (const float*)d_in[1];
    const float* bq    = (const float*)d_in[2];
    const float* wk    = (const float*)d_in[3];
    const float* bk    = (const float*)d_in[4];
    const float* wv    = (const float*)d_in[5];
    const float* bv    = (const float*)d_in[6];
    const float* wo    = (const float*)d_in[7];
    const float* bo    = (const float*)d_in[8];
    const float* g1    = (const float*)d_in[9];
    const float* beta1 = (const float*)d_in[10];
    const float* g2    = (const float*)d_in[11];
    const float* beta2 = (const float*)d_in[12];
    const float* w1    = (const float*)d_in[13];
    const float* bf1   = (const float*)d_in[14];
    const float* w2    = (const float*)d_in[15];
    const float* bf2   = (const float*)d_in[16];

    float *Qp, *Kp, *Vp, *AOp, *R1p, *MIDp, *SC1, *SH1, *SC2, *SH2;
    cudaGetSymbolAddress((void**)&Qp,   g_Q);
    cudaGetSymbolAddress((void**)&Kp,   g_K);
    cudaGetSymbolAddress((void**)&Vp,   g_V);
    cudaGetSymbolAddress((void**)&AOp,  g_AO);
    cudaGetSymbolAddress((void**)&R1p,  g_R1);
    cudaGetSymbolAddress((void**)&MIDp, g_MID);
    cudaGetSymbolAddress((void**)&SC1,  g_scale1);
    cudaGetSymbolAddress((void**)&SH1,  g_shift1);
    cudaGetSymbolAddress((void**)&SC2,  g_scale2);
    cudaGetSymbolAddress((void**)&SH2,  g_shift2);

    const int SMEM = 65536;
    cudaFuncSetAttribute(gemm_tc<1, true >, cudaFuncAttributeMaxDynamicSharedMemorySize, SMEM);
    cudaFuncSetAttribute(gemm_tc<2, false>, cudaFuncAttributeMaxDynamicSharedMemorySize, SMEM);
    cudaFuncSetAttribute(gemm_tc<3, true >, cudaFuncAttributeMaxDynamicSharedMemorySize, SMEM);
    cudaFuncSetAttribute(gemm_tc<4, false>, cudaFuncAttributeMaxDynamicSharedMemorySize, SMEM);
    cudaFuncSetAttribute(attn_tc,           cudaFuncAttributeMaxDynamicSharedMemorySize, ATT_SMEM);

    // BN1 stats
    zero_acc_kernel<<<1, 1024>>>();
    bn_stats_kernel<<<256, 256>>>(x);
    bn_finalize_kernel<<<1, 256>>>(g1, beta1, 0);

    // QKV projections (BN1 fused on A load), outputs in (B,H,N,D)
    gemm_tc<1, true ><<<dim3(2, 256), 256, SMEM>>>(x, wq, bq, nullptr, Qp, MROWS, CCH, CCH, SC1, SH1);
    gemm_tc<1, true ><<<dim3(2, 256), 256, SMEM>>>(x, wk, bk, nullptr, Kp, MROWS, CCH, CCH, SC1, SH1);
    gemm_tc<1, true ><<<dim3(2, 256), 256, SMEM>>>(x, wv, bv, nullptr, Vp, MROWS, CCH, CCH, SC1, SH1);

    // attention (tensor-core flash)
    attn_tc<<<dim3(NTOK / 128, BB * HH), 256, ATT_SMEM>>>(Qp, Kp, Vp, AOp);

    // O projection + residual + BN2 stats
    gemm_tc<2, false><<<dim3(2, 256), 256, SMEM>>>(AOp, wo, bo, x, R1p, MROWS, CCH, CCH, nullptr, nullptr);
    bn_finalize_kernel<<<1, 256>>>(g2, beta2, 1);

    // MLP
    gemm_tc<3, true ><<<dim3(8, 256), 256, SMEM>>>(R1p, w1, bf1, nullptr, MIDp, MROWS, FF, CCH, SC2, SH2);
    gemm_tc<4, false><<<dim3(2, 256), 256, SMEM>>>(MIDp, w2, bf2, R1p, (float*)d_out, MROWS, CCH, FF, nullptr, nullptr);
}

// round 7
// speedup vs baseline: 3.0854x; 1.1192x over previous
#include <cuda_runtime.h>
#include <math.h>
#include <stdint.h>

#define BB   32
#define NTOK 1024
#define CCH  256
#define HH   4
#define DD   64
#define FF   1024
#define MROWS (BB * NTOK)   // 32768
#define EPSV 1e-5f

// ---------------- static device scratch ----------------
__device__ float g_acc[1024];                 // [0:256) sum1, [256:512) sq1, [512:768) sum2, [768:1024) sq2
__device__ float g_scale1[CCH], g_shift1[CCH];
__device__ float g_scale2[CCH], g_shift2[CCH];
__device__ float g_XN [(size_t)MROWS * CCH];  // BN1-normalized x
__device__ float g_H2 [(size_t)MROWS * CCH];  // BN2-normalized R1
__device__ float g_Q  [(size_t)MROWS * CCH];  // (B,H,N,D)
__device__ float g_K  [(size_t)MROWS * CCH];
__device__ float g_V  [(size_t)MROWS * CCH];
__device__ float g_AO [(size_t)MROWS * CCH];  // attention out (B,N,C)
__device__ float g_R1 [(size_t)MROWS * CCH];  // residual 1
__device__ float g_MID[(size_t)MROWS * FF];   // MLP hidden

// ---------------- small kernels ----------------
__global__ void zero_acc_kernel() {
    g_acc[threadIdx.x] = 0.f;
}

__global__ void bn_stats_kernel(const float* __restrict__ x) {
    int c  = threadIdx.x;
    int r0 = blockIdx.x * 128;
    const float* p = x + (size_t)r0 * CCH + c;
    float s = 0.f, q = 0.f;
#pragma unroll 4
    for (int i = 0; i < 128; i++) {
        float v = p[(size_t)i * CCH];
        s += v;
        q += v * v;
    }
    atomicAdd(&g_acc[c],        s);
    atomicAdd(&g_acc[CCH + c],  q);
}

__global__ void bn_finalize_kernel(const float* __restrict__ g,
                                   const float* __restrict__ beta, int which) {
    int c = threadIdx.x;
    float invn = 1.f / (float)MROWS;
    float mean = g_acc[which * 512 + c] * invn;
    float var  = g_acc[which * 512 + 256 + c] * invn - mean * mean;
    float sc   = g[c] * rsqrtf(var + EPSV);
    float sh   = beta[c] - mean * sc;
    if (which == 0) { g_scale1[c] = sc; g_shift1[c] = sh; }
    else            { g_scale2[c] = sc; g_shift2[c] = sh; }
}

// out[i] = in[i] * scale[c] + shift[c], float4-vectorized
__global__ __launch_bounds__(256)
void normalize_kernel(const float* __restrict__ in, float* __restrict__ out, int which) {
    const int idx = blockIdx.x * 256 + threadIdx.x;
    const int c = (idx * 4) & (CCH - 1);
    const float* sc = which ? g_scale2 : g_scale1;
    const float* sh = which ? g_shift2 : g_shift1;
    float4 v = ((const float4*)in)[idx];
    float4 o;
    o.x = v.x * sc[c]     + sh[c];
    o.y = v.y * sc[c + 1] + sh[c + 1];
    o.z = v.z * sc[c + 2] + sh[c + 2];
    o.w = v.w * sc[c + 3] + sh[c + 3];
    ((float4*)out)[idx] = o;
}

// ---------------- tf32 helpers ----------------
__device__ __forceinline__ uint32_t f2tf(float x) {
    uint32_t r;
    asm("cvt.rna.tf32.f32 %0, %1;" : "=r"(r) : "f"(x));
    return r;
}

__device__ __forceinline__ void mma8(float* c, const uint32_t* a, const uint32_t* b) {
    asm volatile(
        "mma.sync.aligned.m16n8k8.row.col.f32.tf32.tf32.f32 "
        "{%0,%1,%2,%3}, {%4,%5,%6,%7}, {%8,%9}, {%0,%1,%2,%3};"
        : "+f"(c[0]), "+f"(c[1]), "+f"(c[2]), "+f"(c[3])
        : "r"(a[0]), "r"(a[1]), "r"(a[2]), "r"(a[3]), "r"(b[0]), "r"(b[1]));
}

#define CP16(dst, src) \
    asm volatile("cp.async.cg.shared.global [%0], [%1], 16;" :: "r"(dst), "l"(src))
#define CPCOMMIT() asm volatile("cp.async.commit_group;")
#define CPWAIT2()  asm volatile("cp.async.wait_group 2;")

// ---------------- tf32 tensor-core NT GEMM, cp.async 3-stage ----------------
// CTA tile 128x128, BK=32, 8 warps of 64x32, 2 CTAs/SM.
// Raw fp32 bits used as tf32 operands (HW truncates mantissa); BN pre-applied.
// EPI: 1 = +bias, store (B,H,N,D)   2 = +bias+res, store, BN2 stats
//      3 = +bias, ReLU              4 = +bias+res (final out)
template<int EPI>
__global__ __launch_bounds__(256, 2)
void gemm_tc(const float* __restrict__ A, const float* __restrict__ Bw,
             const float* __restrict__ bias, const float* __restrict__ res,
             float* __restrict__ out, int M, int N, int K) {
    extern __shared__ float smem[];            // 3 stages x (A 4096 | B 4096) = 96 KB
    __shared__ float ssum[128];
    __shared__ float ssq[128];

    const int tid  = threadIdx.x;
    const int lane = tid & 31;
    const int w    = tid >> 5;
    const int g    = lane >> 2;
    const int tk   = lane & 3;
    const int wm   = w & 1, wn = w >> 1;
    const int mw0  = wm * 64, nw0 = wn * 32;
    const int bx   = blockIdx.x, by = blockIdx.y;

    if (EPI == 2 && tid < 128) { ssum[tid] = 0.f; ssq[tid] = 0.f; }

    const int rowL = tid >> 1;               // 0..127
    const int colL = (tid & 1) * 16;         // 0 or 16
    const float* AptG = A  + (size_t)(by * 128 + rowL) * K + colL;
    const float* BptG = Bw + (size_t)(bx * 128 + rowL) * K + colL;
    const uint32_t sbase = (uint32_t)__cvta_generic_to_shared(smem);
    const int sw = rowL & 7;
    const uint32_t dstA0 = sbase + (uint32_t)(rowL * 32) * 4u;

#define CPA(S, KT)                                                            \
    do {                                                                      \
        const uint32_t da = dstA0 + (uint32_t)(S) * 8192u * 4u;               \
        _Pragma("unroll")                                                     \
        for (int f = 0; f < 4; f++) {                                         \
            const int k4 = (colL >> 2) + f;                                   \
            const uint32_t off = (uint32_t)((k4 ^ sw) << 2) * 4u;             \
            CP16(da + off,              AptG + (KT) + f * 4);                 \
            CP16(da + off + 16384u,     BptG + (KT) + f * 4);                 \
        }                                                                     \
        CPCOMMIT();                                                           \
    } while (0)

#define COMPUTE_KS(KS)                                                        \
    do {                                                                      \
        const int o0 = ((((KS) * 2)     ^ g) << 2) + tk;                      \
        const int o1 = ((((KS) * 2 + 1) ^ g) << 2) + tk;                      \
        uint32_t bf[4][2];                                                    \
        _Pragma("unroll")                                                     \
        for (int j = 0; j < 4; j++) {                                         \
            const float* bp = Bsb + (nw0 + j * 8 + g) * 32;                   \
            bf[j][0] = __float_as_uint(bp[o0]);                               \
            bf[j][1] = __float_as_uint(bp[o1]);                               \
        }                                                                     \
        _Pragma("unroll")                                                     \
        for (int i = 0; i < 4; i++) {                                         \
            const float* ap = Asb + (mw0 + i * 16 + g) * 32;                  \
            uint32_t af[4];                                                   \
            af[0] = __float_as_uint(ap[o0]);                                  \
            af[1] = __float_as_uint(ap[o0 + 256]);                            \
            af[2] = __float_as_uint(ap[o1]);                                  \
            af[3] = __float_as_uint(ap[o1 + 256]);                            \
            _Pragma("unroll")                                                 \
            for (int j = 0; j < 4; j++) mma8(acc[i][j], af, bf[j]);           \
        }                                                                     \
    } while (0)

    float acc[4][4][4];
#pragma unroll
    for (int i = 0; i < 4; i++)
#pragma unroll
        for (int j = 0; j < 4; j++)
#pragma unroll
            for (int q = 0; q < 4; q++) acc[i][j][q] = 0.f;

    // prologue: 3 stages in flight
    CPA(0, 0);
    CPA(1, 32);
    CPA(2, 64);

    const int T = K >> 5;      // K/32 tiles (K >= 96 always)
    int st = 0;
    for (int t = 0; t < T; t++) {
        CPWAIT2();
        __syncthreads();
        const float* Asb = smem + st * 8192;
        const float* Bsb = Asb + 4096;
        COMPUTE_KS(0);
        COMPUTE_KS(1);
        COMPUTE_KS(2);
        COMPUTE_KS(3);
        __syncthreads();
        if (t + 3 < T) CPA(st, (t + 3) * 32);
        else           CPCOMMIT();          // empty group keeps wait_group count aligned
        st = (st == 2) ? 0 : st + 1;
    }
#undef CPA
#undef COMPUTE_KS

    // ---------------- epilogue ----------------
    const int r_base = by * 128 + mw0 + g;
    const int c_glob = bx * 128 + nw0 + 2 * tk;
#pragma unroll
    for (int j = 0; j < 4; j++) {
        const int c0 = c_glob + j * 8;
        const float bv0 = bias[c0], bv1 = bias[c0 + 1];
        float cs0 = 0.f, cq0 = 0.f, cs1 = 0.f, cq1 = 0.f;
#pragma unroll
        for (int i = 0; i < 4; i++) {
#pragma unroll
            for (int rr = 0; rr < 2; rr++) {
                const int m = r_base + i * 16 + rr * 8;
                float v0 = acc[i][j][rr * 2 + 0] + bv0;
                float v1 = acc[i][j][rr * 2 + 1] + bv1;
                if (EPI == 2 || EPI == 4) {
                    const float2 rv = *(const float2*)(res + (size_t)m * N + c0);
                    v0 += rv.x; v1 += rv.y;
                }
                if (EPI == 3) { v0 = fmaxf(v0, 0.f); v1 = fmaxf(v1, 0.f); }
                if (EPI == 1) {
                    const int h = c0 >> 6, d = c0 & 63;
                    const int b = m >> 10, n = m & 1023;
                    float2 t2; t2.x = v0; t2.y = v1;
                    *(float2*)(out + (((size_t)(b * HH + h) * NTOK + n) * DD + d)) = t2;
                } else {
                    float2 t2; t2.x = v0; t2.y = v1;
                    *(float2*)(out + (size_t)m * N + c0) = t2;
                }
                if (EPI == 2) { cs0 += v0; cq0 += v0 * v0; cs1 += v1; cq1 += v1 * v1; }
            }
        }
        if (EPI == 2) {
            const int lc = nw0 + j * 8 + 2 * tk;
            atomicAdd(&ssum[lc],     cs0); atomicAdd(&ssq[lc],     cq0);
            atomicAdd(&ssum[lc + 1], cs1); atomicAdd(&ssq[lc + 1], cq1);
        }
    }
    if (EPI == 2) {
        __syncthreads();
        if (tid < 128) {
            atomicAdd(&g_acc[512 + bx * 128 + tid], ssum[tid]);
            atomicAdd(&g_acc[768 + bx * 128 + tid], ssq[tid]);
        }
    }
}

// ---------------- tensor-core flash attention (unchanged from R6) ----------------
#define KS_STRIDE 68
#define VS_STRIDE 132
#define ATT_SMEM ((128 * KS_STRIDE + 64 * VS_STRIDE) * 4)

__global__ __launch_bounds__(256, 1)
void attn_tc(const float* __restrict__ Q, const float* __restrict__ Kg,
             const float* __restrict__ Vg, float* __restrict__ O) {
    extern __shared__ float smem[];
    float* Ks = smem;                       // 128*68
    float* Vs = smem + 128 * KS_STRIDE;     // 64*132

    const int tid  = threadIdx.x;
    const int lane = tid & 31;
    const int w    = tid >> 5;
    const int g    = lane >> 2;
    const int tk   = lane & 3;
    const int bh   = blockIdx.y;
    const int qt   = blockIdx.x;
    const int b    = bh >> 2, h = bh & 3;
    const size_t hoff = (size_t)bh * NTOK * DD;
    const float* Qh = Q  + hoff;
    const float* Kh = Kg + hoff;
    const float* Vh = Vg + hoff;
    const int q0 = qt * 128;

    float4 kst[8], vst[8];

#define AFETCH(KT)                                                              \
    do {                                                                        \
        _Pragma("unroll")                                                       \
        for (int i = 0; i < 8; i++) {                                           \
            const int lin = tid + 256 * i;                                      \
            const int kr = lin >> 4, c4 = lin & 15;                             \
            kst[i] = *(const float4*)(Kh + (size_t)((KT) + kr) * DD + c4 * 4);  \
            const int vc4 = lin >> 7, vk = lin & 127;                           \
            vst[i] = *(const float4*)(Vh + (size_t)((KT) + vk) * DD + vc4 * 4); \
        }                                                                       \
    } while (0)

#define ASTORE()                                                                \
    do {                                                                        \
        _Pragma("unroll")                                                       \
        for (int i = 0; i < 8; i++) {                                           \
            const int lin = tid + 256 * i;                                      \
            const int kr = lin >> 4, c4 = lin & 15;                             \
            uint4 t4; t4.x = f2tf(kst[i].x); t4.y = f2tf(kst[i].y);             \
                      t4.z = f2tf(kst[i].z); t4.w = f2tf(kst[i].w);             \
            *(uint4*)(Ks + kr * KS_STRIDE + c4 * 4) = t4;                       \
            const int vc4 = lin >> 7, vk = lin & 127;                           \
            Vs[(vc4 * 4 + 0) * VS_STRIDE + vk] = __uint_as_float(f2tf(vst[i].x)); \
            Vs[(vc4 * 4 + 1) * VS_STRIDE + vk] = __uint_as_float(f2tf(vst[i].y)); \
            Vs[(vc4 * 4 + 2) * VS_STRIDE + vk] = __uint_as_float(f2tf(vst[i].z)); \
            Vs[(vc4 * 4 + 3) * VS_STRIDE + vk] = __uint_as_float(f2tf(vst[i].w)); \
        }                                                                       \
    } while (0)

    AFETCH(0);

#pragma unroll
    for (int i = 0; i < 8; i++) {
        const int lin = tid + 256 * i;
        const int r = lin >> 4, c4 = lin & 15;
        float4 qv = *(const float4*)(Qh + (size_t)(q0 + r) * DD + c4 * 4);
        uint4 t4;
        t4.x = f2tf(qv.x * 0.125f); t4.y = f2tf(qv.y * 0.125f);
        t4.z = f2tf(qv.z * 0.125f); t4.w = f2tf(qv.w * 0.125f);
        *(uint4*)(Ks + r * KS_STRIDE + c4 * 4) = t4;
    }
    __syncthreads();

    uint32_t qa[8][4];
    {
        const float* qr0 = Ks + (w * 16 + g) * KS_STRIDE;
        const float* qr1 = qr0 + 8 * KS_STRIDE;
#pragma unroll
        for (int ks = 0; ks < 8; ks++) {
            qa[ks][0] = __float_as_uint(qr0[ks * 8 + tk]);
            qa[ks][1] = __float_as_uint(qr1[ks * 8 + tk]);
            qa[ks][2] = __float_as_uint(qr0[ks * 8 + tk + 4]);
            qa[ks][3] = __float_as_uint(qr1[ks * 8 + tk + 4]);
        }
    }

    float oacc[8][4];
#pragma unroll
    for (int n = 0; n < 8; n++)
#pragma unroll
        for (int q = 0; q < 4; q++) oacc[n][q] = 0.f;
    float m_g = -INFINITY, m_h = -INFINITY, l_g = 0.f, l_h = 0.f;

    const int src0 = (lane & 28) | (tk >> 1);
    const int src1 = src0 + 2;
    const bool odd = (tk & 1);

#pragma unroll 1
    for (int kt8 = 0; kt8 < 8; kt8++) {
        __syncthreads();
        ASTORE();
        __syncthreads();
        if (kt8 < 7) AFETCH((kt8 + 1) * 128);

        float sacc[16][4];
#pragma unroll
        for (int j = 0; j < 16; j++)
#pragma unroll
            for (int q = 0; q < 4; q++) sacc[j][q] = 0.f;

#pragma unroll
        for (int j = 0; j < 16; j++) {
            const float* krow = Ks + (j * 8 + g) * KS_STRIDE;
#pragma unroll
            for (int ks = 0; ks < 8; ks++) {
                uint32_t kb[2];
                kb[0] = __float_as_uint(krow[ks * 8 + tk]);
                kb[1] = __float_as_uint(krow[ks * 8 + tk + 4]);
                mma8(sacc[j], qa[ks], kb);
            }
        }

        float tg = -INFINITY, th = -INFINITY;
#pragma unroll
        for (int j = 0; j < 16; j++) {
            tg = fmaxf(tg, fmaxf(sacc[j][0], sacc[j][1]));
            th = fmaxf(th, fmaxf(sacc[j][2], sacc[j][3]));
        }
        tg = fmaxf(tg, __shfl_xor_sync(0xffffffffu, tg, 1));
        tg = fmaxf(tg, __shfl_xor_sync(0xffffffffu, tg, 2));
        th = fmaxf(th, __shfl_xor_sync(0xffffffffu, th, 1));
        th = fmaxf(th, __shfl_xor_sync(0xffffffffu, th, 2));
        const float mg_new = fmaxf(m_g, tg);
        const float mh_new = fmaxf(m_h, th);
        const float cg = __expf(m_g - mg_new);
        const float ch = __expf(m_h - mh_new);
        m_g = mg_new; m_h = mh_new;
        l_g *= cg; l_h *= ch;
#pragma unroll
        for (int n = 0; n < 8; n++) {
            oacc[n][0] *= cg; oacc[n][1] *= cg;
            oacc[n][2] *= ch; oacc[n][3] *= ch;
        }
#pragma unroll
        for (int j = 0; j < 16; j++) {
            const float p0 = __expf(sacc[j][0] - m_g);
            const float p1 = __expf(sacc[j][1] - m_g);
            const float p2 = __expf(sacc[j][2] - m_h);
            const float p3 = __expf(sacc[j][3] - m_h);
            l_g += p0 + p1;  l_h += p2 + p3;
            sacc[j][0] = __uint_as_float(f2tf(p0));
            sacc[j][1] = __uint_as_float(f2tf(p1));
            sacc[j][2] = __uint_as_float(f2tf(p2));
            sacc[j][3] = __uint_as_float(f2tf(p3));
        }

#pragma unroll
        for (int ks = 0; ks < 16; ks++) {
            const float e00 = __shfl_sync(0xffffffffu, sacc[ks][0], src0);
            const float e01 = __shfl_sync(0xffffffffu, sacc[ks][1], src0);
            const float e10 = __shfl_sync(0xffffffffu, sacc[ks][2], src0);
            const float e11 = __shfl_sync(0xffffffffu, sacc[ks][3], src0);
            const float f00 = __shfl_sync(0xffffffffu, sacc[ks][0], src1);
            const float f01 = __shfl_sync(0xffffffffu, sacc[ks][1], src1);
            const float f10 = __shfl_sync(0xffffffffu, sacc[ks][2], src1);
            const float f11 = __shfl_sync(0xffffffffu, sacc[ks][3], src1);
            uint32_t pa[4];
            pa[0] = __float_as_uint(odd ? e01 : e00);
            pa[1] = __float_as_uint(odd ? e11 : e10);
            pa[2] = __float_as_uint(odd ? f01 : f00);
            pa[3] = __float_as_uint(odd ? f11 : f10);
#pragma unroll
            for (int n = 0; n < 8; n++) {
                const float* vr = Vs + (n * 8 + g) * VS_STRIDE + ks * 8;
                uint32_t vb[2];
                vb[0] = __float_as_uint(vr[tk]);
                vb[1] = __float_as_uint(vr[tk + 4]);
                mma8(oacc[n], pa, vb);
            }
        }
    }
#undef AFETCH
#undef ASTORE

    l_g += __shfl_xor_sync(0xffffffffu, l_g, 1);
    l_g += __shfl_xor_sync(0xffffffffu, l_g, 2);
    l_h += __shfl_xor_sync(0xffffffffu, l_h, 1);
    l_h += __shfl_xor_sync(0xffffffffu, l_h, 2);
    const float ig = 1.f / l_g;
    const float ih = 1.f / l_h;

    const int rg = b * NTOK + q0 + w * 16 + g;
    const int cbase = h * DD + 2 * tk;
#pragma unroll
    for (int n = 0; n < 8; n++) {
        float2 t0; t0.x = oacc[n][0] * ig; t0.y = oacc[n][1] * ig;
        *(float2*)(O + (size_t)rg * CCH + cbase + n * 8) = t0;
        float2 t1; t1.x = oacc[n][2] * ih; t1.y = oacc[n][3] * ih;
        *(float2*)(O + (size_t)(rg + 8) * CCH + cbase + n * 8) = t1;
    }
}

// ---------------- host launcher ----------------
extern "C" void kernel_launch(void* const* d_in, const int* in_sizes, int n_in,
                              void* d_out, int out_size) {
    const float* x     = (const float*)d_in[0];
    const float* wq    = (const float*)d_in[1];
    const float* bq    = (const float*)d_in[2];
    const float* wk    = (const float*)d_in[3];
    const float* bk    = (const float*)d_in[4];
    const float* wv    = (const float*)d_in[5];
    const float* bv    = (const float*)d_in[6];
    const float* wo    = (const float*)d_in[7];
    const float* bo    = (const float*)d_in[8];
    const float* g1    = (const float*)d_in[9];
    const float* beta1 = (const float*)d_in[10];
    const float* g2    = (const float*)d_in[11];
    const float* beta2 = (const float*)d_in[12];
    const float* w1    = (const float*)d_in[13];
    const float* bf1   = (const float*)d_in[14];
    const float* w2    = (const float*)d_in[15];
    const float* bf2   = (const float*)d_in[16];

    float *XNp, *H2p, *Qp, *Kp, *Vp, *AOp, *R1p, *MIDp;
    cudaGetSymbolAddress((void**)&XNp,  g_XN);
    cudaGetSymbolAddress((void**)&H2p,  g_H2);
    cudaGetSymbolAddress((void**)&Qp,   g_Q);
    cudaGetSymbolAddress((void**)&Kp,   g_K);
    cudaGetSymbolAddress((void**)&Vp,   g_V);
    cudaGetSymbolAddress((void**)&AOp,  g_AO);
    cudaGetSymbolAddress((void**)&R1p,  g_R1);
    cudaGetSymbolAddress((void**)&MIDp, g_MID);

    const int SMEM = 98304;   // 3 stages x 32 KB
    cudaFuncSetAttribute(gemm_tc<1>, cudaFuncAttributeMaxDynamicSharedMemorySize, SMEM);
    cudaFuncSetAttribute(gemm_tc<2>, cudaFuncAttributeMaxDynamicSharedMemorySize, SMEM);
    cudaFuncSetAttribute(gemm_tc<3>, cudaFuncAttributeMaxDynamicSharedMemorySize, SMEM);
    cudaFuncSetAttribute(gemm_tc<4>, cudaFuncAttributeMaxDynamicSharedMemorySize, SMEM);
    cudaFuncSetAttribute(attn_tc,    cudaFuncAttributeMaxDynamicSharedMemorySize, ATT_SMEM);

    const int NRM_GRID = (MROWS * CCH / 4) / 256;   // 8192

    // BN1: stats -> finalize -> normalize x
    zero_acc_kernel<<<1, 1024>>>();
    bn_stats_kernel<<<256, 256>>>(x);
    bn_finalize_kernel<<<1, 256>>>(g1, beta1, 0);
    normalize_kernel<<<NRM_GRID, 256>>>(x, XNp, 0);

    // QKV projections, outputs in (B,H,N,D)
    gemm_tc<1><<<dim3(2, 256), 256, SMEM>>>(XNp, wq, bq, nullptr, Qp, MROWS, CCH, CCH);
    gemm_tc<1><<<dim3(2, 256), 256, SMEM>>>(XNp, wk, bk, nullptr, Kp, MROWS, CCH, CCH);
    gemm_tc<1><<<dim3(2, 256), 256, SMEM>>>(XNp, wv, bv, nullptr, Vp, MROWS, CCH, CCH);

    // attention (tensor-core flash)
    attn_tc<<<dim3(NTOK / 128, BB * HH), 256, ATT_SMEM>>>(Qp, Kp, Vp, AOp);

    // O projection + residual + BN2 stats, then normalize R1 -> H2
    gemm_tc<2><<<dim3(2, 256), 256, SMEM>>>(AOp, wo, bo, x, R1p, MROWS, CCH, CCH);
    bn_finalize_kernel<<<1, 256>>>(g2, beta2, 1);
    normalize_kernel<<<NRM_GRID, 256>>>(R1p, H2p, 1);

    // MLP
    gemm_tc<3><<<dim3(8, 256), 256, SMEM>>>(H2p, w1, bf1, nullptr, MIDp, MROWS, FF, CCH);
    gemm_tc<4><<<dim3(2, 256), 256, SMEM>>>(MIDp, w2, bf2, R1p, (float*)d_out, MROWS, CCH, FF);
}

// round 8
// speedup vs baseline: 3.2949x; 1.0679x over previous
#include <cuda_runtime.h>
#include <math.h>
#include <stdint.h>

#define BB   32
#define NTOK 1024
#define CCH  256
#define HH   4
#define DD   64
#define FF   1024
#define MROWS (BB * NTOK)   // 32768
#define EPSV 1e-5f

// ---------------- static device scratch ----------------
__device__ float g_acc[1024];
__device__ float g_scale1[CCH], g_shift1[CCH];
__device__ float g_scale2[CCH], g_shift2[CCH];
__device__ float g_XN [(size_t)MROWS * CCH];  // BN1-normalized x
__device__ float g_H2 [(size_t)MROWS * CCH];  // BN2-normalized R1
__device__ float g_Q  [(size_t)MROWS * CCH];  // (B,H,N,D)
__device__ float g_K  [(size_t)MROWS * CCH];
__device__ float g_V  [(size_t)MROWS * CCH];
__device__ float g_AO [(size_t)MROWS * CCH];
__device__ float g_R1 [(size_t)MROWS * CCH];
__device__ float g_MID[(size_t)MROWS * FF];

// ---------------- small kernels ----------------
__global__ void zero_acc_kernel() {
    g_acc[threadIdx.x] = 0.f;
}

__global__ void bn_stats_kernel(const float* __restrict__ x) {
    int c  = threadIdx.x;
    int r0 = blockIdx.x * 128;
    const float* p = x + (size_t)r0 * CCH + c;
    float s = 0.f, q = 0.f;
#pragma unroll 4
    for (int i = 0; i < 128; i++) {
        float v = p[(size_t)i * CCH];
        s += v;
        q += v * v;
    }
    atomicAdd(&g_acc[c],        s);
    atomicAdd(&g_acc[CCH + c],  q);
}

__global__ void bn_finalize_kernel(const float* __restrict__ g,
                                   const float* __restrict__ beta, int which) {
    int c = threadIdx.x;
    float invn = 1.f / (float)MROWS;
    float mean = g_acc[which * 512 + c] * invn;
    float var  = g_acc[which * 512 + 256 + c] * invn - mean * mean;
    float sc   = g[c] * rsqrtf(var + EPSV);
    float sh   = beta[c] - mean * sc;
    if (which == 0) { g_scale1[c] = sc; g_shift1[c] = sh; }
    else            { g_scale2[c] = sc; g_shift2[c] = sh; }
}

__global__ __launch_bounds__(256)
void normalize_kernel(const float* __restrict__ in, float* __restrict__ out, int which) {
    const int idx = blockIdx.x * 256 + threadIdx.x;
    const int c = (idx * 4) & (CCH - 1);
    const float* sc = which ? g_scale2 : g_scale1;
    const float* sh = which ? g_shift2 : g_shift1;
    float4 v = ((const float4*)in)[idx];
    float4 o;
    o.x = v.x * sc[c]     + sh[c];
    o.y = v.y * sc[c + 1] + sh[c + 1];
    o.z = v.z * sc[c + 2] + sh[c + 2];
    o.w = v.w * sc[c + 3] + sh[c + 3];
    ((float4*)out)[idx] = o;
}

// ---------------- tf32 helpers ----------------
__device__ __forceinline__ uint32_t f2tf(float x) {
    uint32_t r;
    asm("cvt.rna.tf32.f32 %0, %1;" : "=r"(r) : "f"(x));
    return r;
}

__device__ __forceinline__ void mma8(float* c, const uint32_t* a, const uint32_t* b) {
    asm volatile(
        "mma.sync.aligned.m16n8k8.row.col.f32.tf32.tf32.f32 "
        "{%0,%1,%2,%3}, {%4,%5,%6,%7}, {%8,%9}, {%0,%1,%2,%3};"
        : "+f"(c[0]), "+f"(c[1]), "+f"(c[2]), "+f"(c[3])
        : "r"(a[0]), "r"(a[1]), "r"(a[2]), "r"(a[3]), "r"(b[0]), "r"(b[1]));
}

__device__ __forceinline__ void ldsm_x4(uint32_t* r, uint32_t addr) {
    asm volatile("ldmatrix.sync.aligned.m8n8.x4.shared.b16 {%0,%1,%2,%3}, [%4];"
                 : "=r"(r[0]), "=r"(r[1]), "=r"(r[2]), "=r"(r[3]) : "r"(addr));
}

#define CP16(dst, src) \
    asm volatile("cp.async.cg.shared.global [%0], [%1], 16;" :: "r"(dst), "l"(src))
#define CPCOMMIT() asm volatile("cp.async.commit_group;")
#define CPWAIT1()  asm volatile("cp.async.wait_group 1;")

// ---------------- tf32 tensor-core NT GEMM, cp.async 3-stage + ldmatrix ----------------
// CTA tile 128x128, BK=32, 8 warps of 64x32, 2 CTAs/SM.
// Fragments via ldmatrix.x4.b16 (tf32 row of 4 elems = one 16B b16-tile row).
// EPI: 1 = +bias, store (B,H,N,D)   2 = +bias+res, store, BN2 stats
//      3 = +bias, ReLU              4 = +bias+res (final out)
template<int EPI>
__global__ __launch_bounds__(256, 2)
void gemm_tc(const float* __restrict__ A, const float* __restrict__ Bw,
             const float* __restrict__ bias, const float* __restrict__ res,
             float* __restrict__ out, int M, int N, int K) {
    extern __shared__ float smem[];            // 3 stages x (A 16KB | B 16KB) = 96 KB
    __shared__ float ssum[128];
    __shared__ float ssq[128];

    const int tid  = threadIdx.x;
    const int lane = tid & 31;
    const int w    = tid >> 5;
    const int g    = lane >> 2;
    const int tk   = lane & 3;
    const int wm   = w & 1, wn = w >> 1;
    const int mw0  = wm * 64, nw0 = wn * 32;
    const int bx   = blockIdx.x, by = blockIdx.y;

    if (EPI == 2 && tid < 128) { ssum[tid] = 0.f; ssq[tid] = 0.f; }

    // cp.async producer mapping
    const int rowL = tid >> 1;               // 0..127
    const int colL = (tid & 1) * 16;         // 0 or 16
    const float* AptG = A  + (size_t)(by * 128 + rowL) * K + colL;
    const float* BptG = Bw + (size_t)(bx * 128 + rowL) * K + colL;
    const uint32_t sbase = (uint32_t)__cvta_generic_to_shared(smem);
    const int sw = rowL & 7;
    const uint32_t dstA0 = sbase + (uint32_t)(rowL * 32) * 4u;

    // ldmatrix consumer mapping (per-lane tile-row providers)
    const int rsel = lane & 7;               // row within 8-row tile
    const int tsel = lane >> 3;              // which of 4 tiles this lane addresses
    const int rA   = mw0 + ((tsel & 1) << 3) + rsel;   // A: tiles 0,2 rows g; 1,3 rows g+8
    const int kA   = tsel >> 1;                         // A: tiles 0,1 even kg; 2,3 odd
    const int rB   = nw0 + ((tsel >> 1) << 3) + rsel;  // B: tiles 0,1 j; 2,3 j+1
    const int kB   = tsel & 1;                          // B: tiles 0,2 even kg; 1,3 odd

#define CPA(S, KT)                                                            \
    do {                                                                      \
        const uint32_t da = dstA0 + (uint32_t)(S) * 32768u;                   \
        _Pragma("unroll")                                                     \
        for (int f = 0; f < 4; f++) {                                         \
            const int k4 = (colL >> 2) + f;                                   \
            const uint32_t off = (uint32_t)((k4 ^ sw) << 2) * 4u;             \
            CP16(da + off,          AptG + (KT) + f * 4);                     \
            CP16(da + off + 16384u, BptG + (KT) + f * 4);                     \
        }                                                                     \
        CPCOMMIT();                                                           \
    } while (0)

#define COMPUTE_KS(KS)                                                        \
    do {                                                                      \
        const uint32_t axor = (uint32_t)(((((KS) << 1) | kA) ^ rsel) << 4);   \
        const uint32_t bxor = (uint32_t)(((((KS) << 1) | kB) ^ rsel) << 4);   \
        uint32_t bq[8];                                                       \
        ldsm_x4(bq,     sBst + (uint32_t)(rB * 128) + bxor);                  \
        ldsm_x4(bq + 4, sBst + (uint32_t)((rB + 16) * 128) + bxor);           \
        _Pragma("unroll")                                                     \
        for (int i = 0; i < 4; i++) {                                         \
            uint32_t af[4];                                                   \
            ldsm_x4(af, sAst + (uint32_t)((rA + 16 * i) * 128) + axor);       \
            mma8(acc[i][0], af, bq);                                          \
            mma8(acc[i][1], af, bq + 2);                                      \
            mma8(acc[i][2], af, bq + 4);                                      \
            mma8(acc[i][3], af, bq + 6);                                      \
        }                                                                     \
    } while (0)

    float acc[4][4][4];
#pragma unroll
    for (int i = 0; i < 4; i++)
#pragma unroll
        for (int j = 0; j < 4; j++)
#pragma unroll
            for (int q = 0; q < 4; q++) acc[i][j][q] = 0.f;

    // prologue: 2 stages in flight
    CPA(0, 0);
    CPA(1, 32);

    const int T = K >> 5;
    int st = 0;
    for (int t = 0; t < T; t++) {
        CPWAIT1();                 // own groups: tile t landed
        __syncthreads();           // all threads' tile-t data visible; tile t-1 fully consumed
        if (t + 2 < T) {
            const int s2 = (st == 0) ? 2 : st - 1;   // (st+2)%3
            CPA(s2, (t + 2) * 32);
        } else {
            CPCOMMIT();            // keep group accounting uniform
        }
        const uint32_t sAst = sbase + (uint32_t)st * 32768u;
        const uint32_t sBst = sAst + 16384u;
        COMPUTE_KS(0);
        COMPUTE_KS(1);
        COMPUTE_KS(2);
        COMPUTE_KS(3);
        st = (st == 2) ? 0 : st + 1;
    }
#undef CPA
#undef COMPUTE_KS

    // ---------------- epilogue ----------------
    const int r_base = by * 128 + mw0 + g;
    const int c_glob = bx * 128 + nw0 + 2 * tk;
#pragma unroll
    for (int j = 0; j < 4; j++) {
        const int c0 = c_glob + j * 8;
        const float bv0 = bias[c0], bv1 = bias[c0 + 1];
        float cs0 = 0.f, cq0 = 0.f, cs1 = 0.f, cq1 = 0.f;
#pragma unroll
        for (int i = 0; i < 4; i++) {
#pragma unroll
            for (int rr = 0; rr < 2; rr++) {
                const int m = r_base + i * 16 + rr * 8;
                float v0 = acc[i][j][rr * 2 + 0] + bv0;
                float v1 = acc[i][j][rr * 2 + 1] + bv1;
                if (EPI == 2 || EPI == 4) {
                    const float2 rv = *(const float2*)(res + (size_t)m * N + c0);
                    v0 += rv.x; v1 += rv.y;
                }
                if (EPI == 3) { v0 = fmaxf(v0, 0.f); v1 = fmaxf(v1, 0.f); }
                if (EPI == 1) {
                    const int h = c0 >> 6, d = c0 & 63;
                    const int b = m >> 10, n = m & 1023;
                    float2 t2; t2.x = v0; t2.y = v1;
                    *(float2*)(out + (((size_t)(b * HH + h) * NTOK + n) * DD + d)) = t2;
                } else {
                    float2 t2; t2.x = v0; t2.y = v1;
                    *(float2*)(out + (size_t)m * N + c0) = t2;
                }
                if (EPI == 2) { cs0 += v0; cq0 += v0 * v0; cs1 += v1; cq1 += v1 * v1; }
            }
        }
        if (EPI == 2) {
            const int lc = nw0 + j * 8 + 2 * tk;
            atomicAdd(&ssum[lc],     cs0); atomicAdd(&ssq[lc],     cq0);
            atomicAdd(&ssum[lc + 1], cs1); atomicAdd(&ssq[lc + 1], cq1);
        }
    }
    if (EPI == 2) {
        __syncthreads();
        if (tid < 128) {
            atomicAdd(&g_acc[512 + bx * 128 + tid], ssum[tid]);
            atomicAdd(&g_acc[768 + bx * 128 + tid], ssq[tid]);
        }
    }
}

// ---------------- tensor-core flash attention (unchanged from R7) ----------------
#define KS_STRIDE 68
#define VS_STRIDE 132
#define ATT_SMEM ((128 * KS_STRIDE + 64 * VS_STRIDE) * 4)

__global__ __launch_bounds__(256, 1)
void attn_tc(const float* __restrict__ Q, const float* __restrict__ Kg,
             const float* __restrict__ Vg, float* __restrict__ O) {
    extern __shared__ float smem[];
    float* Ks = smem;
    float* Vs = smem + 128 * KS_STRIDE;

    const int tid  = threadIdx.x;
    const int lane = tid & 31;
    const int w    = tid >> 5;
    const int g    = lane >> 2;
    const int tk   = lane & 3;
    const int bh   = blockIdx.y;
    const int qt   = blockIdx.x;
    const int b    = bh >> 2, h = bh & 3;
    const size_t hoff = (size_t)bh * NTOK * DD;
    const float* Qh = Q  + hoff;
    const float* Kh = Kg + hoff;
    const float* Vh = Vg + hoff;
    const int q0 = qt * 128;

    float4 kst[8], vst[8];

#define AFETCH(KT)                                                              \
    do {                                                                        \
        _Pragma("unroll")                                                       \
        for (int i = 0; i < 8; i++) {                                           \
            const int lin = tid + 256 * i;                                      \
            const int kr = lin >> 4, c4 = lin & 15;                             \
            kst[i] = *(const float4*)(Kh + (size_t)((KT) + kr) * DD + c4 * 4);  \
            const int vc4 = lin >> 7, vk = lin & 127;                           \
            vst[i] = *(const float4*)(Vh + (size_t)((KT) + vk) * DD + vc4 * 4); \
        }                                                                       \
    } while (0)

#define ASTORE()                                                                \
    do {                                                                        \
        _Pragma("unroll")                                                       \
        for (int i = 0; i < 8; i++) {                                           \
            const int lin = tid + 256 * i;                                      \
            const int kr = lin >> 4, c4 = lin & 15;                             \
            uint4 t4; t4.x = f2tf(kst[i].x); t4.y = f2tf(kst[i].y);             \
                      t4.z = f2tf(kst[i].z); t4.w = f2tf(kst[i].w);             \
            *(uint4*)(Ks + kr * KS_STRIDE + c4 * 4) = t4;                       \
            const int vc4 = lin >> 7, vk = lin & 127;                           \
            Vs[(vc4 * 4 + 0) * VS_STRIDE + vk] = __uint_as_float(f2tf(vst[i].x)); \
            Vs[(vc4 * 4 + 1) * VS_STRIDE + vk] = __uint_as_float(f2tf(vst[i].y)); \
            Vs[(vc4 * 4 + 2) * VS_STRIDE + vk] = __uint_as_float(f2tf(vst[i].z)); \
            Vs[(vc4 * 4 + 3) * VS_STRIDE + vk] = __uint_as_float(f2tf(vst[i].w)); \
        }                                                                       \
    } while (0)

    AFETCH(0);

#pragma unroll
    for (int i = 0; i < 8; i++) {
        const int lin = tid + 256 * i;
        const int r = lin >> 4, c4 = lin & 15;
        float4 qv = *(const float4*)(Qh + (size_t)(q0 + r) * DD + c4 * 4);
        uint4 t4;
        t4.x = f2tf(qv.x * 0.125f); t4.y = f2tf(qv.y * 0.125f);
        t4.z = f2tf(qv.z * 0.125f); t4.w = f2tf(qv.w * 0.125f);
        *(uint4*)(Ks + r * KS_STRIDE + c4 * 4) = t4;
    }
    __syncthreads();

    uint32_t qa[8][4];
    {
        const float* qr0 = Ks + (w * 16 + g) * KS_STRIDE;
        const float* qr1 = qr0 + 8 * KS_STRIDE;
#pragma unroll
        for (int ks = 0; ks < 8; ks++) {
            qa[ks][0] = __float_as_uint(qr0[ks * 8 + tk]);
            qa[ks][1] = __float_as_uint(qr1[ks * 8 + tk]);
            qa[ks][2] = __float_as_uint(qr0[ks * 8 + tk + 4]);
            qa[ks][3] = __float_as_uint(qr1[ks * 8 + tk + 4]);
        }
    }

    float oacc[8][4];
#pragma unroll
    for (int n = 0; n < 8; n++)
#pragma unroll
        for (int q = 0; q < 4; q++) oacc[n][q] = 0.f;
    float m_g = -INFINITY, m_h = -INFINITY, l_g = 0.f, l_h = 0.f;

    const int src0 = (lane & 28) | (tk >> 1);
    const int src1 = src0 + 2;
    const bool odd = (tk & 1);

#pragma unroll 1
    for (int kt8 = 0; kt8 < 8; kt8++) {
        __syncthreads();
        ASTORE();
        __syncthreads();
        if (kt8 < 7) AFETCH((kt8 + 1) * 128);

        float sacc[16][4];
#pragma unroll
        for (int j = 0; j < 16; j++)
#pragma unroll
            for (int q = 0; q < 4; q++) sacc[j][q] = 0.f;

#pragma unroll
        for (int j = 0; j < 16; j++) {
            const float* krow = Ks + (j * 8 + g) * KS_STRIDE;
#pragma unroll
            for (int ks = 0; ks < 8; ks++) {
                uint32_t kb[2];
                kb[0] = __float_as_uint(krow[ks * 8 + tk]);
                kb[1] = __float_as_uint(krow[ks * 8 + tk + 4]);
                mma8(sacc[j], qa[ks], kb);
            }
        }

        float tg = -INFINITY, th = -INFINITY;
#pragma unroll
        for (int j = 0; j < 16; j++) {
            tg = fmaxf(tg, fmaxf(sacc[j][0], sacc[j][1]));
            th = fmaxf(th, fmaxf(sacc[j][2], sacc[j][3]));
        }
        tg = fmaxf(tg, __shfl_xor_sync(0xffffffffu, tg, 1));
        tg = fmaxf(tg, __shfl_xor_sync(0xffffffffu, tg, 2));
        th = fmaxf(th, __shfl_xor_sync(0xffffffffu, th, 1));
        th = fmaxf(th, __shfl_xor_sync(0xffffffffu, th, 2));
        const float mg_new = fmaxf(m_g, tg);
        const float mh_new = fmaxf(m_h, th);
        const float cg = __expf(m_g - mg_new);
        const float ch = __expf(m_h - mh_new);
        m_g = mg_new; m_h = mh_new;
        l_g *= cg; l_h *= ch;
#pragma unroll
        for (int n = 0; n < 8; n++) {
            oacc[n][0] *= cg; oacc[n][1] *= cg;
            oacc[n][2] *= ch; oacc[n][3] *= ch;
        }
#pragma unroll
        for (int j = 0; j < 16; j++) {
            const float p0 = __expf(sacc[j][0] - m_g);
            const float p1 = __expf(sacc[j][1] - m_g);
            const float p2 = __expf(sacc[j][2] - m_h);
            const float p3 = __expf(sacc[j][3] - m_h);
            l_g += p0 + p1;  l_h += p2 + p3;
            sacc[j][0] = __uint_as_float(f2tf(p0));
            sacc[j][1] = __uint_as_float(f2tf(p1));
            sacc[j][2] = __uint_as_float(f2tf(p2));
            sacc[j][3] = __uint_as_float(f2tf(p3));
        }

#pragma unroll
        for (int ks = 0; ks < 16; ks++) {
            const float e00 = __shfl_sync(0xffffffffu, sacc[ks][0], src0);
            const float e01 = __shfl_sync(0xffffffffu, sacc[ks][1], src0);
            const float e10 = __shfl_sync(0xffffffffu, sacc[ks][2], src0);
            const float e11 = __shfl_sync(0xffffffffu, sacc[ks][3], src0);
            const float f00 = __shfl_sync(0xffffffffu, sacc[ks][0], src1);
            const float f01 = __shfl_sync(0xffffffffu, sacc[ks][1], src1);
            const float f10 = __shfl_sync(0xffffffffu, sacc[ks][2], src1);
            const float f11 = __shfl_sync(0xffffffffu, sacc[ks][3], src1);
            uint32_t pa[4];
            pa[0] = __float_as_uint(odd ? e01 : e00);
            pa[1] = __float_as_uint(odd ? e11 : e10);
            pa[2] = __float_as_uint(odd ? f01 : f00);
            pa[3] = __float_as_uint(odd ? f11 : f10);
#pragma unroll
            for (int n = 0; n < 8; n++) {
                const float* vr = Vs + (n * 8 + g) * VS_STRIDE + ks * 8;
                uint32_t vb[2];
                vb[0] = __float_as_uint(vr[tk]);
                vb[1] = __float_as_uint(vr[tk + 4]);
                mma8(oacc[n], pa, vb);
            }
        }
    }
#undef AFETCH
#undef ASTORE

    l_g += __shfl_xor_sync(0xffffffffu, l_g, 1);
    l_g += __shfl_xor_sync(0xffffffffu, l_g, 2);
    l_h += __shfl_xor_sync(0xffffffffu, l_h, 1);
    l_h += __shfl_xor_sync(0xffffffffu, l_h, 2);
    const float ig = 1.f / l_g;
    const float ih = 1.f / l_h;

    const int rg = b * NTOK + q0 + w * 16 + g;
    const int cbase = h * DD + 2 * tk;
#pragma unroll
    for (int n = 0; n < 8; n++) {
        float2 t0; t0.x = oacc[n][0] * ig; t0.y = oacc[n][1] * ig;
        *(float2*)(O + (size_t)rg * CCH + cbase + n * 8) = t0;
        float2 t1; t1.x = oacc[n][2] * ih; t1.y = oacc[n][3] * ih;
        *(float2*)(O + (size_t)(rg + 8) * CCH + cbase + n * 8) = t1;
    }
}

// ---------------- host launcher ----------------
extern "C" void kernel_launch(void* const* d_in, const int* in_sizes, int n_in,
                              void* d_out, int out_size) {
    const float* x     = (const float*)d_in[0];
    const float* wq    = (const float*)d_in[1];
    const float* bq    = (const float*)d_in[2];
    const float* wk    = (const float*)d_in[3];
    const float* bk    = (const float*)d_in[4];
    const float* wv    = (const float*)d_in[5];
    const float* bv    = (const float*)d_in[6];
    const float* wo    = (const float*)d_in[7];
    const float* bo    = (const float*)d_in[8];
    const float* g1    = (const float*)d_in[9];
    const float* beta1 = (const float*)d_in[10];
    const float* g2    = (const float*)d_in[11];
    const float* beta2 = (const float*)d_in[12];
    const float* w1    = (const float*)d_in[13];
    const float* bf1   = (const float*)d_in[14];
    const float* w2    = (const float*)d_in[15];
    const float* bf2   = (const float*)d_in[16];

    float *XNp, *H2p, *Qp, *Kp, *Vp, *AOp, *R1p, *MIDp;
    cudaGetSymbolAddress((void**)&XNp,  g_XN);
    cudaGetSymbolAddress((void**)&H2p,  g_H2);
    cudaGetSymbolAddress((void**)&Qp,   g_Q);
    cudaGetSymbolAddress((void**)&Kp,   g_K);
    cudaGetSymbolAddress((void**)&Vp,   g_V);
    cudaGetSymbolAddress((void**)&AOp,  g_AO);
    cudaGetSymbolAddress((void**)&R1p,  g_R1);
    cudaGetSymbolAddress((void**)&MIDp, g_MID);

    const int SMEM = 98304;   // 3 stages x 32 KB
    cudaFuncSetAttribute(gemm_tc<1>, cudaFuncAttributeMaxDynamicSharedMemorySize, SMEM);
    cudaFuncSetAttribute(gemm_tc<2>, cudaFuncAttributeMaxDynamicSharedMemorySize, SMEM);
    cudaFuncSetAttribute(gemm_tc<3>, cudaFuncAttributeMaxDynamicSharedMemorySize, SMEM);
    cudaFuncSetAttribute(gemm_tc<4>, cudaFuncAttributeMaxDynamicSharedMemorySize, SMEM);
    cudaFuncSetAttribute(attn_tc,    cudaFuncAttributeMaxDynamicSharedMemorySize, ATT_SMEM);

    const int NRM_GRID = (MROWS * CCH / 4) / 256;   // 8192

    // BN1: stats -> finalize -> normalize x
    zero_acc_kernel<<<1, 1024>>>();
    bn_stats_kernel<<<256, 256>>>(x);
    bn_finalize_kernel<<<1, 256>>>(g1, beta1, 0);
    normalize_kernel<<<NRM_GRID, 256>>>(x, XNp, 0);

    // QKV projections, outputs in (B,H,N,D)
    gemm_tc<1><<<dim3(2, 256), 256, SMEM>>>(XNp, wq, bq, nullptr, Qp, MROWS, CCH, CCH);
    gemm_tc<1><<<dim3(2, 256), 256, SMEM>>>(XNp, wk, bk, nullptr, Kp, MROWS, CCH, CCH);
    gemm_tc<1><<<dim3(2, 256), 256, SMEM>>>(XNp, wv, bv, nullptr, Vp, MROWS, CCH, CCH);

    // attention (tensor-core flash)
    attn_tc<<<dim3(NTOK / 128, BB * HH), 256, ATT_SMEM>>>(Qp, Kp, Vp, AOp);

    // O projection + residual + BN2 stats, then normalize R1 -> H2
    gemm_tc<2><<<dim3(2, 256), 256, SMEM>>>(AOp, wo, bo, x, R1p, MROWS, CCH, CCH);
    bn_finalize_kernel<<<1, 256>>>(g2, beta2, 1);
    normalize_kernel<<<NRM_GRID, 256>>>(R1p, H2p, 1);

    // MLP
    gemm_tc<3><<<dim3(8, 256), 256, SMEM>>>(H2p, w1, bf1, nullptr, MIDp, MROWS, FF, CCH);
    gemm_tc<4><<<dim3(2, 256), 256, SMEM>>>(MIDp, w2, bf2, R1p, (float*)d_out, MROWS, CCH, FF);
}